// round 11
// baseline (speedup 1.0000x reference)
#include <cuda_runtime.h>
#include <cuda_fp16.h>
#include <math.h>
#include <stdint.h>

#define S_LEN 2048
#define DIM 2560
#define N_HEAD 32
#define HEAD_DIM 80
#define ROT_DIM 32
#define INTER 10240
#define EPS 1e-5f

// ---------------- fp32 scratch ----------------
__device__ float g_qkv [S_LEN * 3 * DIM];
__device__ float g_q   [N_HEAD * S_LEN * HEAD_DIM];
__device__ float g_k   [N_HEAD * S_LEN * HEAD_DIM];
__device__ float g_v   [N_HEAD * S_LEN * HEAD_DIM];
__device__ float g_attn[S_LEN * DIM];

// ---------------- fp16 hi/lo splits ----------------
__device__ __half s_wqkv_h[3 * DIM * DIM], s_wqkv_l[3 * DIM * DIM];
__device__ __half s_wo_h  [DIM * DIM],     s_wo_l  [DIM * DIM];
__device__ __half s_w1_h  [INTER * DIM],   s_w1_l  [INTER * DIM];
__device__ __half s_w2_h  [DIM * INTER],   s_w2_l  [DIM * INTER];
__device__ __half s_h_h   [S_LEN * DIM],   s_h_l   [S_LEN * DIM];
__device__ __half s_y_h   [S_LEN * DIM],   s_y_l   [S_LEN * DIM];
__device__ __half s_f_h   [S_LEN * INTER], s_f_l   [S_LEN * INTER];

// ---------------- helpers ----------------
__device__ __forceinline__ uint32_t smem_u32(const void* p) {
    uint32_t a;
    asm("{ .reg .u64 t; cvta.to.shared.u64 t, %1; cvt.u32.u64 %0, t; }" : "=r"(a) : "l"(p));
    return a;
}
__device__ __forceinline__ uint32_t pkh(__half a, __half b) {
    __half2 t = __halves2half2(a, b);
    return *(uint32_t*)&t;
}
__device__ __forceinline__ void ldsm4(uint32_t r[4], uint32_t addr) {
    asm volatile("ldmatrix.sync.aligned.m8n8.x4.shared.b16 {%0,%1,%2,%3}, [%4];"
                 : "=r"(r[0]), "=r"(r[1]), "=r"(r[2]), "=r"(r[3]) : "r"(addr));
}
__device__ __forceinline__ void mma16816(float c[4], const uint32_t a[4], const uint32_t b[2]) {
    asm volatile("mma.sync.aligned.m16n8k16.row.col.f32.f16.f16.f32 "
                 "{%0,%1,%2,%3}, {%4,%5,%6,%7}, {%8,%9}, {%0,%1,%2,%3};"
                 : "+f"(c[0]), "+f"(c[1]), "+f"(c[2]), "+f"(c[3])
                 : "r"(a[0]), "r"(a[1]), "r"(a[2]), "r"(a[3]), "r"(b[0]), "r"(b[1]));
}
__device__ __forceinline__ float gelu_tanh(float v) {
    float c = v + 0.044715f * v * v * v;
    return 0.5f * v * (1.f + tanhf(0.7978845608028654f * c));
}

// ---------------- fp32 -> fp16 hi/lo split (vectorized) ----------------
__global__ __launch_bounds__(256)
void split_kernel(const float* __restrict__ src, __half* __restrict__ dh,
                  __half* __restrict__ dl, int n4)
{
    const int stride = gridDim.x * 256;
    for (int i = blockIdx.x * 256 + threadIdx.x; i < n4; i += stride) {
        float4 v = *(const float4*)(src + (size_t)i * 4);
        __half h0 = __float2half_rn(v.x), h1 = __float2half_rn(v.y);
        __half h2 = __float2half_rn(v.z), h3 = __float2half_rn(v.w);
        __half l0 = __float2half_rn(v.x - __half2float(h0));
        __half l1 = __float2half_rn(v.y - __half2float(h1));
        __half l2 = __float2half_rn(v.z - __half2float(h2));
        __half l3 = __float2half_rn(v.w - __half2float(h3));
        *(uint2*)(dh + (size_t)i * 4) = make_uint2(pkh(h0, h1), pkh(h2, h3));
        *(uint2*)(dl + (size_t)i * 4) = make_uint2(pkh(l0, l1), pkh(l2, l3));
    }
}

// ---------------- mma.sync fp16x3 GEMM, cp.async 2-stage, 2 CTAs/SM ----------------
#define BK 32
#define LDT 40
#define TILE_HH (128 * LDT)
#define TILE_B  (TILE_HH * 2)        // 10240
#define STAGE_B (4 * TILE_B)         // 40960
#define NSTAGE 2
#define SMEM_DYN (NSTAGE * STAGE_B)  // 81920 -> 2 CTAs/SM

// EPI: 0 -> fp32 C; 1 -> gelu then split to Ch/Cl; 2 -> fp32 C + res1 + res2
template<int EPI>
__global__ __launch_bounds__(256)
void mma_gemm(const __half* __restrict__ Ah_, const __half* __restrict__ Al_,
              const __half* __restrict__ Wh_, const __half* __restrict__ Wl_,
              const float* __restrict__ bias,
              float* __restrict__ C, __half* __restrict__ Ch, __half* __restrict__ Cl,
              int M, int N, int K,
              const float* __restrict__ res1, const float* __restrict__ res2)
{
    extern __shared__ __align__(16) char smem[];
    const uint32_t sb = smem_u32(smem);
    const int tid = threadIdx.x;
    const int lane = tid & 31;
    const int wid  = tid >> 5;
    const int wm = (wid & 3) * 32;
    const int wn = (wid >> 2) * 64;
    const int m0 = blockIdx.x * 128;
    const int n0 = blockIdx.y * 128;
    const int nch = K / BK;

    // cp.async source mapping: threads 0-63 Ah, 64-127 Al, 128-191 Wh, 192-255 Wl
    const int tile = tid >> 6;
    const int t64  = tid & 63;
    const __half* gsrc = (tile == 0 ? Ah_ : (tile == 1 ? Al_ : (tile == 2 ? Wh_ : Wl_)));
    gsrc += (size_t)((tile < 2 ? m0 : n0) + t64 * 2) * K;
    const uint32_t sdst0 = (uint32_t)tile * TILE_B + (uint32_t)(t64 * 2) * (LDT * 2);

    auto issue = [&](int ch, int st) {
        if (ch < nch) {
            const int k0 = ch * BK;
            const uint32_t sbase = sb + st * STAGE_B + sdst0;
            #pragma unroll
            for (int j = 0; j < 8; j++) {
                const int rj  = j >> 2;
                const int seg = j & 3;
                const __half* gp = gsrc + (size_t)rj * K + k0 + seg * 8;
                const uint32_t dst = sbase + (uint32_t)(rj * LDT + seg * 8) * 2;
                asm volatile("cp.async.cg.shared.global [%0], [%1], 16;" :: "r"(dst), "l"(gp));
            }
        }
        asm volatile("cp.async.commit_group;" ::: "memory");
    };

    float acc[2][8][4];
    #pragma unroll
    for (int i = 0; i < 2; i++)
        #pragma unroll
        for (int j = 0; j < 8; j++)
            #pragma unroll
            for (int q = 0; q < 4; q++) acc[i][j][q] = 0.f;

    const int a_row    = wm + (lane & 15);
    const int a_colsel = (lane >> 4) << 3;
    const int b_rowsel = ((lane >> 4) & 1) * 8 + (lane & 7);
    const int b_colsel = ((lane >> 3) & 1) * 8;

    auto compute = [&](int st) {
        const uint32_t base = sb + st * STAGE_B;
        #pragma unroll
        for (int ks = 0; ks < 2; ks++) {
            const int kb = ks * 16;
            uint32_t ah[2][4], al[2][4], bh[8][2], bl[8][2];
            #pragma unroll
            for (int i = 0; i < 2; i++) {
                const uint32_t off = ((a_row + i * 16) * LDT + kb + a_colsel) * 2;
                ldsm4(ah[i], base + off);
                ldsm4(al[i], base + TILE_B + off);
            }
            #pragma unroll
            for (int p = 0; p < 4; p++) {
                const int nrow = wn + p * 16 + b_rowsel;
                const uint32_t off = (nrow * LDT + kb + b_colsel) * 2;
                uint32_t t[4];
                ldsm4(t, base + 2 * TILE_B + off);
                bh[2 * p][0] = t[0]; bh[2 * p][1] = t[1];
                bh[2 * p + 1][0] = t[2]; bh[2 * p + 1][1] = t[3];
                ldsm4(t, base + 3 * TILE_B + off);
                bl[2 * p][0] = t[0]; bl[2 * p][1] = t[1];
                bl[2 * p + 1][0] = t[2]; bl[2 * p + 1][1] = t[3];
            }
            #pragma unroll
            for (int i = 0; i < 2; i++)
                #pragma unroll
                for (int j = 0; j < 8; j++) mma16816(acc[i][j], ah[i], bh[j]);
            #pragma unroll
            for (int i = 0; i < 2; i++)
                #pragma unroll
                for (int j = 0; j < 8; j++) mma16816(acc[i][j], ah[i], bl[j]);
            #pragma unroll
            for (int i = 0; i < 2; i++)
                #pragma unroll
                for (int j = 0; j < 8; j++) mma16816(acc[i][j], al[i], bh[j]);
        }
    };

    issue(0, 0);
    issue(1, 1);
    for (int ch = 0; ch < nch; ch++) {
        const int st = ch & 1;
        asm volatile("cp.async.wait_group 1;" ::: "memory");
        __syncthreads();
        compute(st);
        __syncthreads();          // all warps done reading stage st
        issue(ch + 2, st);        // overwrite it; completes while stage st^1 computes
    }

    // ---- epilogue ----
    #pragma unroll
    for (int i = 0; i < 2; i++) {
        const int row = m0 + wm + i * 16 + (lane >> 2);
        #pragma unroll
        for (int j = 0; j < 8; j++) {
            const int col = n0 + wn + j * 8 + (lane & 3) * 2;
            const float b0 = bias[col], b1 = bias[col + 1];
            #pragma unroll
            for (int half_ = 0; half_ < 2; half_++) {
                const int r = row + half_ * 8;
                float v0 = acc[i][j][half_ * 2 + 0] + b0;
                float v1 = acc[i][j][half_ * 2 + 1] + b1;
                const size_t off = (size_t)r * N + col;
                if (EPI == 1) {
                    v0 = gelu_tanh(v0); v1 = gelu_tanh(v1);
                    __half h0 = __float2half_rn(v0), h1 = __float2half_rn(v1);
                    __half l0 = __float2half_rn(v0 - __half2float(h0));
                    __half l1 = __float2half_rn(v1 - __half2float(h1));
                    *(uint32_t*)(Ch + off) = pkh(h0, h1);
                    *(uint32_t*)(Cl + off) = pkh(l0, l1);
                } else {
                    if (EPI == 2) {
                        float2 r1 = *(const float2*)(res1 + off);
                        float2 r2 = *(const float2*)(res2 + off);
                        v0 += r1.x + r2.x; v1 += r1.y + r2.y;
                    }
                    *(float2*)(C + off) = make_float2(v0, v1);
                }
            }
        }
    }
}

// ---------------- LayerNorm -> fp16 hi/lo ----------------
__global__ void ln_kernel(const float* __restrict__ x,
                          const float* __restrict__ w,
                          const float* __restrict__ b)
{
    const int s = blockIdx.x;
    const int tid = threadIdx.x;
    const float* row = x + (size_t)s * DIM;
    float sum = 0.f, sumsq = 0.f;
    for (int i = tid; i < DIM; i += 256) {
        float v = row[i];
        sum += v; sumsq += v * v;
    }
    __shared__ float r1[256], r2[256];
    r1[tid] = sum; r2[tid] = sumsq;
    __syncthreads();
    for (int st = 128; st > 0; st >>= 1) {
        if (tid < st) { r1[tid] += r1[tid + st]; r2[tid] += r2[tid + st]; }
        __syncthreads();
    }
    const float mu  = r1[0] * (1.f / DIM);
    const float var = r2[0] * (1.f / DIM) - mu * mu;
    const float rstd = rsqrtf(var + EPS);
    for (int i = tid; i < DIM; i += 256) {
        const float v = (row[i] - mu) * rstd * w[i] + b[i];
        const size_t off = (size_t)s * DIM + i;
        const __half hv = __float2half_rn(v);
        s_h_h[off] = hv;
        s_h_l[off] = __float2half_rn(v - __half2float(hv));
    }
}

// ---------------- split QKV + RoPE ----------------
__global__ void prep_qkv_kernel(const float* __restrict__ qkv,
                                const int* __restrict__ input_pos)
{
    const int s = blockIdx.x;
    const float pos = (float)input_pos[s];
    const float* row = qkv + (size_t)s * (3 * DIM);
    for (int idx = threadIdx.x; idx < DIM; idx += 256) {
        const int h = idx / HEAD_DIM;
        const int d = idx - h * HEAD_DIM;
        const size_t dsti = ((size_t)h * S_LEN + s) * HEAD_DIM + d;

        float qv = row[idx];
        float kv = row[DIM + idx];
        float vv = row[2 * DIM + idx];

        if (d < ROT_DIM) {
            const int i = (d < 16) ? d : d - 16;
            const float inv = __powf(10000.f, -(float)i / 16.f);
            const float ang = pos * inv;
            const float c = __cosf(ang), sn = __sinf(ang);
            if (d < 16) {
                float q2 = row[idx + 16];
                float k2 = row[DIM + idx + 16];
                qv = qv * c - q2 * sn;
                kv = kv * c - k2 * sn;
            } else {
                float q2 = row[idx - 16];
                float k2 = row[DIM + idx - 16];
                qv = qv * c + q2 * sn;
                kv = kv * c + k2 * sn;
            }
        }
        g_q[dsti] = qv;
        g_k[dsti] = kv;
        g_v[dsti] = vv;
    }
}

// ---------------- flash-style causal attention (writes y hi/lo fp16) ----------------
#define BQ 64
#define BKV 32

__global__ __launch_bounds__(256)
void attn_kernel()
{
    __shared__ float sq[BQ][HEAD_DIM + 1];
    __shared__ float skv[BKV][HEAD_DIM + 1];
    __shared__ float ss[BQ][BKV + 1];

    const int qb = blockIdx.x;
    const int h  = blockIdx.y;
    const int tid = threadIdx.x;
    const int r   = tid & 63;
    const int grp = tid >> 6;
    const int j0  = grp * 8;
    const int d0  = grp * 20;
    const int qi  = qb * BQ + r;
    const float scale = 0.11180339887498949f;

    {
        const float* qg = g_q + ((size_t)h * S_LEN + qb * BQ) * HEAD_DIM;
        for (int i = tid; i < BQ * HEAD_DIM; i += 256)
            sq[i / HEAD_DIM][i % HEAD_DIM] = qg[i];
    }
    __syncthreads();

    float o[20];
    #pragma unroll
    for (int d = 0; d < 20; d++) o[d] = 0.f;
    float m = -INFINITY, l = 0.f;

    const int kb_max = (qb * BQ + BQ - 1) / BKV;
    for (int kb = 0; kb <= kb_max; kb++) {
        const float* kg = g_k + ((size_t)h * S_LEN + kb * BKV) * HEAD_DIM;
        for (int i = tid; i < BKV * HEAD_DIM; i += 256)
            skv[i / HEAD_DIM][i % HEAD_DIM] = kg[i];
        __syncthreads();

        #pragma unroll
        for (int jj = 0; jj < 8; jj++) {
            const int j = j0 + jj;
            const int ki = kb * BKV + j;
            float dot = 0.f;
            #pragma unroll
            for (int dd = 0; dd < HEAD_DIM; dd++)
                dot = fmaf(sq[r][dd], skv[j][dd], dot);
            ss[r][j] = (ki <= qi) ? dot * scale : -1e9f;
        }
        __syncthreads();

        const float* vg = g_v + ((size_t)h * S_LEN + kb * BKV) * HEAD_DIM;
        for (int i = tid; i < BKV * HEAD_DIM; i += 256)
            skv[i / HEAD_DIM][i % HEAD_DIM] = vg[i];
        __syncthreads();

        float mt = -INFINITY;
        #pragma unroll
        for (int j = 0; j < BKV; j++) mt = fmaxf(mt, ss[r][j]);
        const float mnew = fmaxf(m, mt);
        const float alpha = __expf(m - mnew);
        l *= alpha;
        #pragma unroll
        for (int d = 0; d < 20; d++) o[d] *= alpha;
        #pragma unroll
        for (int j = 0; j < BKV; j++) {
            const float p = __expf(ss[r][j] - mnew);
            l += p * 0.25f;
            #pragma unroll
            for (int d = 0; d < 20; d++)
                o[d] = fmaf(p, skv[j][d0 + d], o[d]);
        }
        m = mnew;
        __syncthreads();
    }

    const float inv_l = 1.f / (4.f * l);
    const size_t yoff = (size_t)qi * DIM + h * HEAD_DIM + d0;
    #pragma unroll
    for (int d = 0; d < 20; d++) {
        const float v = o[d] * inv_l;
        const __half hv = __float2half_rn(v);
        s_y_h[yoff + d] = hv;
        s_y_l[yoff + d] = __float2half_rn(v - __half2float(hv));
    }
}

// ---------------- host launch ----------------
extern "C" void kernel_launch(void* const* d_in, const int* in_sizes, int n_in,
                              void* d_out, int out_size)
{
    const float* x       = (const float*)d_in[0];
    const int*   pos     = (const int*)  d_in[1];
    const float* ln_w    = (const float*)d_in[3];
    const float* ln_b    = (const float*)d_in[4];
    const float* wqkv_w  = (const float*)d_in[5];
    const float* wqkv_b  = (const float*)d_in[6];
    const float* wo_w    = (const float*)d_in[7];
    const float* wo_b    = (const float*)d_in[8];
    const float* w1_w    = (const float*)d_in[9];
    const float* w1_b    = (const float*)d_in[10];
    const float* w2_w    = (const float*)d_in[11];
    const float* w2_b    = (const float*)d_in[12];
    float* out = (float*)d_out;

    float *qkv_p, *attn_p;
    cudaGetSymbolAddress((void**)&qkv_p,  g_qkv);
    cudaGetSymbolAddress((void**)&attn_p, g_attn);
    __half *wqkv_h, *wqkv_l, *wo_h, *wo_l, *w1_h, *w1_l, *w2_h, *w2_l;
    __half *h_h, *h_l, *y_h, *y_l, *f_h, *f_l;
    cudaGetSymbolAddress((void**)&wqkv_h, s_wqkv_h); cudaGetSymbolAddress((void**)&wqkv_l, s_wqkv_l);
    cudaGetSymbolAddress((void**)&wo_h,   s_wo_h);   cudaGetSymbolAddress((void**)&wo_l,   s_wo_l);
    cudaGetSymbolAddress((void**)&w1_h,   s_w1_h);   cudaGetSymbolAddress((void**)&w1_l,   s_w1_l);
    cudaGetSymbolAddress((void**)&w2_h,   s_w2_h);   cudaGetSymbolAddress((void**)&w2_l,   s_w2_l);
    cudaGetSymbolAddress((void**)&h_h,    s_h_h);    cudaGetSymbolAddress((void**)&h_l,    s_h_l);
    cudaGetSymbolAddress((void**)&y_h,    s_y_h);    cudaGetSymbolAddress((void**)&y_l,    s_y_l);
    cudaGetSymbolAddress((void**)&f_h,    s_f_h);    cudaGetSymbolAddress((void**)&f_l,    s_f_l);

    cudaFuncSetAttribute(mma_gemm<0>, cudaFuncAttributeMaxDynamicSharedMemorySize, SMEM_DYN);
    cudaFuncSetAttribute(mma_gemm<1>, cudaFuncAttributeMaxDynamicSharedMemorySize, SMEM_DYN);
    cudaFuncSetAttribute(mma_gemm<2>, cudaFuncAttributeMaxDynamicSharedMemorySize, SMEM_DYN);

    // 0. weight splits
    split_kernel<<<1184, 256>>>(wqkv_w, wqkv_h, wqkv_l, 3 * DIM * DIM / 4);
    split_kernel<<<1184, 256>>>(wo_w,   wo_h,   wo_l,   DIM * DIM / 4);
    split_kernel<<<1184, 256>>>(w1_w,   w1_h,   w1_l,   INTER * DIM / 4);
    split_kernel<<<1184, 256>>>(w2_w,   w2_h,   w2_l,   DIM * INTER / 4);

    // 1. LayerNorm -> h hi/lo
    ln_kernel<<<S_LEN, 256>>>(x, ln_w, ln_b);

    // 2. QKV projection (fp32 out for RoPE)
    mma_gemm<0><<<dim3(S_LEN / 128, 3 * DIM / 128), 256, SMEM_DYN>>>(
        h_h, h_l, wqkv_h, wqkv_l, wqkv_b, qkv_p, nullptr, nullptr,
        S_LEN, 3 * DIM, DIM, nullptr, nullptr);

    // 3. split + RoPE
    prep_qkv_kernel<<<S_LEN, 256>>>(qkv_p, pos);

    // 4. attention -> y hi/lo
    attn_kernel<<<dim3(S_LEN / BQ, N_HEAD), 256>>>();

    // 5. output projection -> fp32 attn
    mma_gemm<0><<<dim3(S_LEN / 128, DIM / 128), 256, SMEM_DYN>>>(
        y_h, y_l, wo_h, wo_l, wo_b, attn_p, nullptr, nullptr,
        S_LEN, DIM, DIM, nullptr, nullptr);

    // 6. FFN up + gelu -> f hi/lo
    mma_gemm<1><<<dim3(S_LEN / 128, INTER / 128), 256, SMEM_DYN>>>(
        h_h, h_l, w1_h, w1_l, w1_b, nullptr, f_h, f_l,
        S_LEN, INTER, DIM, nullptr, nullptr);

    // 7. FFN down + residual fuse
    mma_gemm<2><<<dim3(S_LEN / 128, DIM / 128), 256, SMEM_DYN>>>(
        f_h, f_l, w2_h, w2_l, w2_b, out, nullptr, nullptr,
        S_LEN, DIM, INTER, attn_p, x);
}

// round 12
// speedup vs baseline: 1.8253x; 1.8253x over previous
#include <cuda_runtime.h>
#include <cuda_fp16.h>
#include <math.h>
#include <stdint.h>

#define S_LEN 2048
#define DIM 2560
#define N_HEAD 32
#define HEAD_DIM 80
#define ROT_DIM 32
#define INTER 10240
#define EPS 1e-5f

// ---------------- fp32 scratch ----------------
__device__ float g_qkv [S_LEN * 3 * DIM];
__device__ float g_q   [N_HEAD * S_LEN * HEAD_DIM];
__device__ float g_k   [N_HEAD * S_LEN * HEAD_DIM];
__device__ float g_v   [N_HEAD * S_LEN * HEAD_DIM];
__device__ float g_attn[S_LEN * DIM];

// ---------------- fp16 hi/lo splits ----------------
__device__ __half s_wqkv_h[3 * DIM * DIM], s_wqkv_l[3 * DIM * DIM];
__device__ __half s_wo_h  [DIM * DIM],     s_wo_l  [DIM * DIM];
__device__ __half s_w1_h  [INTER * DIM],   s_w1_l  [INTER * DIM];
__device__ __half s_w2_h  [DIM * INTER],   s_w2_l  [DIM * INTER];
__device__ __half s_h_h   [S_LEN * DIM],   s_h_l   [S_LEN * DIM];
__device__ __half s_y_h   [S_LEN * DIM],   s_y_l   [S_LEN * DIM];
__device__ __half s_f_h   [S_LEN * INTER], s_f_l   [S_LEN * INTER];

// ---------------- helpers ----------------
__device__ __forceinline__ uint32_t smem_u32(const void* p) {
    uint32_t a;
    asm("{ .reg .u64 t; cvta.to.shared.u64 t, %1; cvt.u32.u64 %0, t; }" : "=r"(a) : "l"(p));
    return a;
}
__device__ __forceinline__ uint32_t pkh(__half a, __half b) {
    __half2 t = __halves2half2(a, b);
    return *(uint32_t*)&t;
}
__device__ __forceinline__ void ldsm4(uint32_t r[4], uint32_t addr) {
    asm volatile("ldmatrix.sync.aligned.m8n8.x4.shared.b16 {%0,%1,%2,%3}, [%4];"
                 : "=r"(r[0]), "=r"(r[1]), "=r"(r[2]), "=r"(r[3]) : "r"(addr));
}
__device__ __forceinline__ void mma16816(float c[4], const uint32_t a[4], const uint32_t b[2]) {
    asm volatile("mma.sync.aligned.m16n8k16.row.col.f32.f16.f16.f32 "
                 "{%0,%1,%2,%3}, {%4,%5,%6,%7}, {%8,%9}, {%0,%1,%2,%3};"
                 : "+f"(c[0]), "+f"(c[1]), "+f"(c[2]), "+f"(c[3])
                 : "r"(a[0]), "r"(a[1]), "r"(a[2]), "r"(a[3]), "r"(b[0]), "r"(b[1]));
}
__device__ __forceinline__ float gelu_tanh(float v) {
    float c = v + 0.044715f * v * v * v;
    return 0.5f * v * (1.f + tanhf(0.7978845608028654f * c));
}

// ---------------- fp32 -> fp16 hi/lo split (vectorized) ----------------
__global__ __launch_bounds__(256)
void split_kernel(const float* __restrict__ src, __half* __restrict__ dh,
                  __half* __restrict__ dl, int n4)
{
    const int stride = gridDim.x * 256;
    for (int i = blockIdx.x * 256 + threadIdx.x; i < n4; i += stride) {
        float4 v = *(const float4*)(src + (size_t)i * 4);
        __half h0 = __float2half_rn(v.x), h1 = __float2half_rn(v.y);
        __half h2 = __float2half_rn(v.z), h3 = __float2half_rn(v.w);
        __half l0 = __float2half_rn(v.x - __half2float(h0));
        __half l1 = __float2half_rn(v.y - __half2float(h1));
        __half l2 = __float2half_rn(v.z - __half2float(h2));
        __half l3 = __float2half_rn(v.w - __half2float(h3));
        *(uint2*)(dh + (size_t)i * 4) = make_uint2(pkh(h0, h1), pkh(h2, h3));
        *(uint2*)(dl + (size_t)i * 4) = make_uint2(pkh(l0, l1), pkh(l2, l3));
    }
}

// ---------------- mma.sync fp16x3 GEMM, register-staged double buffer (round-5 skeleton) ----------------
#define BK 32
#define LDT 40
#define TILE_HH (128 * LDT)
#define TILE_B  (TILE_HH * 2)        // 10240 bytes
#define BUF_B   (4 * TILE_B)         // Ah|Al|Wh|Wl = 40960
#define SMEM_DYN (2 * BUF_B)         // 81920 -> 2 CTAs/SM

// EPI: 0 -> fp32 C; 1 -> gelu then split to Ch/Cl; 2 -> fp32 C + res1 + res2
template<int EPI>
__global__ __launch_bounds__(256)
void mma_gemm(const __half* __restrict__ Ah_, const __half* __restrict__ Al_,
              const __half* __restrict__ Wh_, const __half* __restrict__ Wl_,
              const float* __restrict__ bias,
              float* __restrict__ C, __half* __restrict__ Ch, __half* __restrict__ Cl,
              int M, int N, int K,
              const float* __restrict__ res1, const float* __restrict__ res2)
{
    extern __shared__ __align__(16) char smem[];
    const uint32_t sb = smem_u32(smem);
    const int tid = threadIdx.x;
    const int lane = tid & 31;
    const int wid  = tid >> 5;
    const int wm = (wid & 3) * 32;
    const int wn = (wid >> 2) * 64;
    const int m0 = blockIdx.x * 128;
    const int n0 = blockIdx.y * 128;
    const int nch = K / BK;

    // per-thread staging map: 8 reps cover 4 tiles x 128 rows x 4 16B-segments
    // idx = rep*256+tid; tile = idx>>9; row = (idx&511)>>2; seg = idx&3
    const __half* gbase[4] = { Ah_, Al_, Wh_, Wl_ };

    uint4 rg[8];
    auto stage = [&](int k0) {
        #pragma unroll
        for (int r = 0; r < 8; r++) {
            const int idx  = r * 256 + tid;
            const int tile = idx >> 9;
            const int rem  = idx & 511;
            const int row  = rem >> 2;
            const int seg  = rem & 3;
            const int base_row = (tile < 2 ? m0 : n0) + row;
            rg[r] = *(const uint4*)(gbase[tile] + (size_t)base_row * K + k0 + seg * 8);
        }
    };
    auto storebuf = [&](int b) {
        const uint32_t bu = sb + b * BUF_B;
        #pragma unroll
        for (int r = 0; r < 8; r++) {
            const int idx  = r * 256 + tid;
            const int tile = idx >> 9;
            const int rem  = idx & 511;
            const int row  = rem >> 2;
            const int seg  = rem & 3;
            const uint32_t dst = bu + (uint32_t)tile * TILE_B + (uint32_t)(row * LDT + seg * 8) * 2;
            asm volatile("st.shared.v4.b32 [%0], {%1,%2,%3,%4};"
                         :: "r"(dst), "r"(rg[r].x), "r"(rg[r].y), "r"(rg[r].z), "r"(rg[r].w));
        }
    };

    float acc[2][8][4];
    #pragma unroll
    for (int i = 0; i < 2; i++)
        #pragma unroll
        for (int j = 0; j < 8; j++)
            #pragma unroll
            for (int q = 0; q < 4; q++) acc[i][j][q] = 0.f;

    const int a_row    = wm + (lane & 15);
    const int a_colsel = (lane >> 4) << 3;
    const int b_rowsel = ((lane >> 4) & 1) * 8 + (lane & 7);
    const int b_colsel = ((lane >> 3) & 1) * 8;

    auto compute = [&](int b) {
        const uint32_t base = sb + b * BUF_B;
        #pragma unroll
        for (int ks = 0; ks < 2; ks++) {
            const int kb = ks * 16;
            uint32_t ah[2][4], al[2][4], bh[8][2], bl[8][2];
            #pragma unroll
            for (int i = 0; i < 2; i++) {
                const uint32_t off = ((a_row + i * 16) * LDT + kb + a_colsel) * 2;
                ldsm4(ah[i], base + off);
                ldsm4(al[i], base + TILE_B + off);
            }
            #pragma unroll
            for (int p = 0; p < 4; p++) {
                const int nrow = wn + p * 16 + b_rowsel;
                const uint32_t off = (nrow * LDT + kb + b_colsel) * 2;
                uint32_t t[4];
                ldsm4(t, base + 2 * TILE_B + off);
                bh[2 * p][0] = t[0]; bh[2 * p][1] = t[1];
                bh[2 * p + 1][0] = t[2]; bh[2 * p + 1][1] = t[3];
                ldsm4(t, base + 3 * TILE_B + off);
                bl[2 * p][0] = t[0]; bl[2 * p][1] = t[1];
                bl[2 * p + 1][0] = t[2]; bl[2 * p + 1][1] = t[3];
            }
            #pragma unroll
            for (int i = 0; i < 2; i++)
                #pragma unroll
                for (int j = 0; j < 8; j++) mma16816(acc[i][j], ah[i], bh[j]);
            #pragma unroll
            for (int i = 0; i < 2; i++)
                #pragma unroll
                for (int j = 0; j < 8; j++) mma16816(acc[i][j], ah[i], bl[j]);
            #pragma unroll
            for (int i = 0; i < 2; i++)
                #pragma unroll
                for (int j = 0; j < 8; j++) mma16816(acc[i][j], al[i], bh[j]);
        }
    };

    stage(0);
    storebuf(0);
    __syncthreads();

    for (int ch = 0; ch < nch; ch++) {
        if (ch + 1 < nch) stage((ch + 1) * BK);   // gmem loads overlap compute below
        compute(ch & 1);
        __syncthreads();
        if (ch + 1 < nch) storebuf((ch + 1) & 1);
        __syncthreads();
    }

    // ---- epilogue ----
    #pragma unroll
    for (int i = 0; i < 2; i++) {
        const int row = m0 + wm + i * 16 + (lane >> 2);
        #pragma unroll
        for (int j = 0; j < 8; j++) {
            const int col = n0 + wn + j * 8 + (lane & 3) * 2;
            const float b0 = bias[col], b1 = bias[col + 1];
            #pragma unroll
            for (int half_ = 0; half_ < 2; half_++) {
                const int r = row + half_ * 8;
                float v0 = acc[i][j][half_ * 2 + 0] + b0;
                float v1 = acc[i][j][half_ * 2 + 1] + b1;
                const size_t off = (size_t)r * N + col;
                if (EPI == 1) {
                    v0 = gelu_tanh(v0); v1 = gelu_tanh(v1);
                    __half h0 = __float2half_rn(v0), h1 = __float2half_rn(v1);
                    __half l0 = __float2half_rn(v0 - __half2float(h0));
                    __half l1 = __float2half_rn(v1 - __half2float(h1));
                    *(uint32_t*)(Ch + off) = pkh(h0, h1);
                    *(uint32_t*)(Cl + off) = pkh(l0, l1);
                } else {
                    if (EPI == 2) {
                        float2 r1 = *(const float2*)(res1 + off);
                        float2 r2 = *(const float2*)(res2 + off);
                        v0 += r1.x + r2.x; v1 += r1.y + r2.y;
                    }
                    *(float2*)(C + off) = make_float2(v0, v1);
                }
            }
        }
    }
}

// ---------------- LayerNorm -> fp16 hi/lo ----------------
__global__ void ln_kernel(const float* __restrict__ x,
                          const float* __restrict__ w,
                          const float* __restrict__ b)
{
    const int s = blockIdx.x;
    const int tid = threadIdx.x;
    const float* row = x + (size_t)s * DIM;
    float sum = 0.f, sumsq = 0.f;
    for (int i = tid; i < DIM; i += 256) {
        float v = row[i];
        sum += v; sumsq += v * v;
    }
    __shared__ float r1[256], r2[256];
    r1[tid] = sum; r2[tid] = sumsq;
    __syncthreads();
    for (int st = 128; st > 0; st >>= 1) {
        if (tid < st) { r1[tid] += r1[tid + st]; r2[tid] += r2[tid + st]; }
        __syncthreads();
    }
    const float mu  = r1[0] * (1.f / DIM);
    const float var = r2[0] * (1.f / DIM) - mu * mu;
    const float rstd = rsqrtf(var + EPS);
    for (int i = tid; i < DIM; i += 256) {
        const float v = (row[i] - mu) * rstd * w[i] + b[i];
        const size_t off = (size_t)s * DIM + i;
        const __half hv = __float2half_rn(v);
        s_h_h[off] = hv;
        s_h_l[off] = __float2half_rn(v - __half2float(hv));
    }
}

// ---------------- split QKV + RoPE ----------------
__global__ void prep_qkv_kernel(const float* __restrict__ qkv,
                                const int* __restrict__ input_pos)
{
    const int s = blockIdx.x;
    const float pos = (float)input_pos[s];
    const float* row = qkv + (size_t)s * (3 * DIM);
    for (int idx = threadIdx.x; idx < DIM; idx += 256) {
        const int h = idx / HEAD_DIM;
        const int d = idx - h * HEAD_DIM;
        const size_t dsti = ((size_t)h * S_LEN + s) * HEAD_DIM + d;

        float qv = row[idx];
        float kv = row[DIM + idx];
        float vv = row[2 * DIM + idx];

        if (d < ROT_DIM) {
            const int i = (d < 16) ? d : d - 16;
            const float inv = __powf(10000.f, -(float)i / 16.f);
            const float ang = pos * inv;
            const float c = __cosf(ang), sn = __sinf(ang);
            if (d < 16) {
                float q2 = row[idx + 16];
                float k2 = row[DIM + idx + 16];
                qv = qv * c - q2 * sn;
                kv = kv * c - k2 * sn;
            } else {
                float q2 = row[idx - 16];
                float k2 = row[DIM + idx - 16];
                qv = qv * c + q2 * sn;
                kv = kv * c + k2 * sn;
            }
        }
        g_q[dsti] = qv;
        g_k[dsti] = kv;
        g_v[dsti] = vv;
    }
}

// ---------------- flash-style causal attention (writes y hi/lo fp16) ----------------
#define BQ 64
#define BKV 32

__global__ __launch_bounds__(256)
void attn_kernel()
{
    __shared__ float sq[BQ][HEAD_DIM + 1];
    __shared__ float skv[BKV][HEAD_DIM + 1];
    __shared__ float ss[BQ][BKV + 1];

    const int qb = blockIdx.x;
    const int h  = blockIdx.y;
    const int tid = threadIdx.x;
    const int r   = tid & 63;
    const int grp = tid >> 6;
    const int j0  = grp * 8;
    const int d0  = grp * 20;
    const int qi  = qb * BQ + r;
    const float scale = 0.11180339887498949f;

    {
        const float* qg = g_q + ((size_t)h * S_LEN + qb * BQ) * HEAD_DIM;
        for (int i = tid; i < BQ * HEAD_DIM; i += 256)
            sq[i / HEAD_DIM][i % HEAD_DIM] = qg[i];
    }
    __syncthreads();

    float o[20];
    #pragma unroll
    for (int d = 0; d < 20; d++) o[d] = 0.f;
    float m = -INFINITY, l = 0.f;

    const int kb_max = (qb * BQ + BQ - 1) / BKV;
    for (int kb = 0; kb <= kb_max; kb++) {
        const float* kg = g_k + ((size_t)h * S_LEN + kb * BKV) * HEAD_DIM;
        for (int i = tid; i < BKV * HEAD_DIM; i += 256)
            skv[i / HEAD_DIM][i % HEAD_DIM] = kg[i];
        __syncthreads();

        #pragma unroll
        for (int jj = 0; jj < 8; jj++) {
            const int j = j0 + jj;
            const int ki = kb * BKV + j;
            float dot = 0.f;
            #pragma unroll
            for (int dd = 0; dd < HEAD_DIM; dd++)
                dot = fmaf(sq[r][dd], skv[j][dd], dot);
            ss[r][j] = (ki <= qi) ? dot * scale : -1e9f;
        }
        __syncthreads();

        const float* vg = g_v + ((size_t)h * S_LEN + kb * BKV) * HEAD_DIM;
        for (int i = tid; i < BKV * HEAD_DIM; i += 256)
            skv[i / HEAD_DIM][i % HEAD_DIM] = vg[i];
        __syncthreads();

        float mt = -INFINITY;
        #pragma unroll
        for (int j = 0; j < BKV; j++) mt = fmaxf(mt, ss[r][j]);
        const float mnew = fmaxf(m, mt);
        const float alpha = __expf(m - mnew);
        l *= alpha;
        #pragma unroll
        for (int d = 0; d < 20; d++) o[d] *= alpha;
        #pragma unroll
        for (int j = 0; j < BKV; j++) {
            const float p = __expf(ss[r][j] - mnew);
            l += p * 0.25f;
            #pragma unroll
            for (int d = 0; d < 20; d++)
                o[d] = fmaf(p, skv[j][d0 + d], o[d]);
        }
        m = mnew;
        __syncthreads();
    }

    const float inv_l = 1.f / (4.f * l);
    const size_t yoff = (size_t)qi * DIM + h * HEAD_DIM + d0;
    #pragma unroll
    for (int d = 0; d < 20; d++) {
        const float v = o[d] * inv_l;
        const __half hv = __float2half_rn(v);
        s_y_h[yoff + d] = hv;
        s_y_l[yoff + d] = __float2half_rn(v - __half2float(hv));
    }
}

// ---------------- host launch ----------------
extern "C" void kernel_launch(void* const* d_in, const int* in_sizes, int n_in,
                              void* d_out, int out_size)
{
    const float* x       = (const float*)d_in[0];
    const int*   pos     = (const int*)  d_in[1];
    const float* ln_w    = (const float*)d_in[3];
    const float* ln_b    = (const float*)d_in[4];
    const float* wqkv_w  = (const float*)d_in[5];
    const float* wqkv_b  = (const float*)d_in[6];
    const float* wo_w    = (const float*)d_in[7];
    const float* wo_b    = (const float*)d_in[8];
    const float* w1_w    = (const float*)d_in[9];
    const float* w1_b    = (const float*)d_in[10];
    const float* w2_w    = (const float*)d_in[11];
    const float* w2_b    = (const float*)d_in[12];
    float* out = (float*)d_out;

    float *qkv_p, *attn_p;
    cudaGetSymbolAddress((void**)&qkv_p,  g_qkv);
    cudaGetSymbolAddress((void**)&attn_p, g_attn);
    __half *wqkv_h, *wqkv_l, *wo_h, *wo_l, *w1_h, *w1_l, *w2_h, *w2_l;
    __half *h_h, *h_l, *y_h, *y_l, *f_h, *f_l;
    cudaGetSymbolAddress((void**)&wqkv_h, s_wqkv_h); cudaGetSymbolAddress((void**)&wqkv_l, s_wqkv_l);
    cudaGetSymbolAddress((void**)&wo_h,   s_wo_h);   cudaGetSymbolAddress((void**)&wo_l,   s_wo_l);
    cudaGetSymbolAddress((void**)&w1_h,   s_w1_h);   cudaGetSymbolAddress((void**)&w1_l,   s_w1_l);
    cudaGetSymbolAddress((void**)&w2_h,   s_w2_h);   cudaGetSymbolAddress((void**)&w2_l,   s_w2_l);
    cudaGetSymbolAddress((void**)&h_h,    s_h_h);    cudaGetSymbolAddress((void**)&h_l,    s_h_l);
    cudaGetSymbolAddress((void**)&y_h,    s_y_h);    cudaGetSymbolAddress((void**)&y_l,    s_y_l);
    cudaGetSymbolAddress((void**)&f_h,    s_f_h);    cudaGetSymbolAddress((void**)&f_l,    s_f_l);

    cudaFuncSetAttribute(mma_gemm<0>, cudaFuncAttributeMaxDynamicSharedMemorySize, SMEM_DYN);
    cudaFuncSetAttribute(mma_gemm<1>, cudaFuncAttributeMaxDynamicSharedMemorySize, SMEM_DYN);
    cudaFuncSetAttribute(mma_gemm<2>, cudaFuncAttributeMaxDynamicSharedMemorySize, SMEM_DYN);

    // 0. weight splits
    split_kernel<<<1184, 256>>>(wqkv_w, wqkv_h, wqkv_l, 3 * DIM * DIM / 4);
    split_kernel<<<1184, 256>>>(wo_w,   wo_h,   wo_l,   DIM * DIM / 4);
    split_kernel<<<1184, 256>>>(w1_w,   w1_h,   w1_l,   INTER * DIM / 4);
    split_kernel<<<1184, 256>>>(w2_w,   w2_h,   w2_l,   DIM * INTER / 4);

    // 1. LayerNorm -> h hi/lo
    ln_kernel<<<S_LEN, 256>>>(x, ln_w, ln_b);

    // 2. QKV projection (fp32 out for RoPE)
    mma_gemm<0><<<dim3(S_LEN / 128, 3 * DIM / 128), 256, SMEM_DYN>>>(
        h_h, h_l, wqkv_h, wqkv_l, wqkv_b, qkv_p, nullptr, nullptr,
        S_LEN, 3 * DIM, DIM, nullptr, nullptr);

    // 3. split + RoPE
    prep_qkv_kernel<<<S_LEN, 256>>>(qkv_p, pos);

    // 4. attention -> y hi/lo
    attn_kernel<<<dim3(S_LEN / BQ, N_HEAD), 256>>>();

    // 5. output projection -> fp32 attn
    mma_gemm<0><<<dim3(S_LEN / 128, DIM / 128), 256, SMEM_DYN>>>(
        y_h, y_l, wo_h, wo_l, wo_b, attn_p, nullptr, nullptr,
        S_LEN, DIM, DIM, nullptr, nullptr);

    // 6. FFN up + gelu -> f hi/lo
    mma_gemm<1><<<dim3(S_LEN / 128, INTER / 128), 256, SMEM_DYN>>>(
        h_h, h_l, w1_h, w1_l, w1_b, nullptr, f_h, f_l,
        S_LEN, INTER, DIM, nullptr, nullptr);

    // 7. FFN down + residual fuse
    mma_gemm<2><<<dim3(S_LEN / 128, DIM / 128), 256, SMEM_DYN>>>(
        f_h, f_l, w2_h, w2_l, w2_b, out, nullptr, nullptr,
        S_LEN, DIM, INTER, attn_p, x);
}

// round 13
// speedup vs baseline: 2.3810x; 1.3044x over previous
#include <cuda_runtime.h>
#include <cuda_fp16.h>
#include <math.h>
#include <stdint.h>

#define S_LEN 2048
#define DIM 2560
#define N_HEAD 32
#define HEAD_DIM 80
#define ROT_DIM 32
#define INTER 10240
#define EPS 1e-5f

// ---------------- scratch ----------------
__device__ float g_h   [S_LEN * DIM];
__device__ float g_qkv [S_LEN * 3 * DIM];
__device__ float g_q   [N_HEAD * S_LEN * HEAD_DIM];
__device__ float g_k   [N_HEAD * S_LEN * HEAD_DIM];
__device__ float g_v   [N_HEAD * S_LEN * HEAD_DIM];
__device__ float g_y   [S_LEN * DIM];
__device__ float g_attn[S_LEN * DIM];
__device__ float g_ffn1[S_LEN * INTER];

// ---------------- helpers ----------------
__device__ __forceinline__ uint32_t smem_u32(const void* p) {
    uint32_t a;
    asm("{ .reg .u64 t; cvta.to.shared.u64 t, %1; cvt.u32.u64 %0, t; }" : "=r"(a) : "l"(p));
    return a;
}
__device__ __forceinline__ uint32_t pkh(__half a, __half b) {
    __half2 t = __halves2half2(a, b);
    return *(uint32_t*)&t;
}
__device__ __forceinline__ void ldsm4(uint32_t r[4], uint32_t addr) {
    asm volatile("ldmatrix.sync.aligned.m8n8.x4.shared.b16 {%0,%1,%2,%3}, [%4];"
                 : "=r"(r[0]), "=r"(r[1]), "=r"(r[2]), "=r"(r[3]) : "r"(addr));
}
__device__ __forceinline__ void mma16816(float c[4], const uint32_t a[4], const uint32_t b[2]) {
    asm volatile("mma.sync.aligned.m16n8k16.row.col.f32.f16.f16.f32 "
                 "{%0,%1,%2,%3}, {%4,%5,%6,%7}, {%8,%9}, {%0,%1,%2,%3};"
                 : "+f"(c[0]), "+f"(c[1]), "+f"(c[2]), "+f"(c[3])
                 : "r"(a[0]), "r"(a[1]), "r"(a[2]), "r"(a[3]), "r"(b[0]), "r"(b[1]));
}
__device__ __forceinline__ float gelu_tanh(float v) {
    float c = v + 0.044715f * v * v * v;
    return 0.5f * v * (1.f + tanhf(0.7978845608028654f * c));
}

// ---------------- mma.sync fp16x2 GEMM: C = A @ W^T + bias ----------------
// A truncated to fp16 (Ah); W kept as Wh+Wl. Products: Ah*Wh + Ah*Wl.
// tiles: BM=128, BN=128, BK=32. smem rows padded to 40 halves (80B stride).
#define BK 32
#define LDT 40
#define TILE_H (128 * LDT)          // halves per tile
#define TILE_B (TILE_H * 2)         // bytes per tile (10240)
#define BUF_H  (3 * TILE_H)         // Ah | Wh | Wl
#define BUF_B  (3 * TILE_B)         // 30720
#define SMEM_DYN (2 * BUF_B)        // 61440

// EPI: 0 plain, 1 gelu, 2 +res1+res2
template<int EPI>
__global__ __launch_bounds__(256)
void mma_gemm(const float* __restrict__ A, const float* __restrict__ W,
              const float* __restrict__ bias, float* __restrict__ C,
              int M, int N, int K,
              const float* __restrict__ res1, const float* __restrict__ res2)
{
    extern __shared__ __align__(16) __half smem[];
    const int tid  = threadIdx.x;
    const int lane = tid & 31;
    const int wid  = tid >> 5;
    const int wm   = (wid & 3) * 32;
    const int wn   = (wid >> 2) * 64;
    const int m0 = blockIdx.x * 128;
    const int n0 = blockIdx.y * 128;

    float acc[2][8][4];
    #pragma unroll
    for (int i = 0; i < 2; i++)
        #pragma unroll
        for (int j = 0; j < 8; j++)
            #pragma unroll
            for (int q = 0; q < 4; q++) acc[i][j][q] = 0.f;

    const int nch = K / BK;

    float4 ra[4], rw[4];

    auto stage = [&](int k0) {
        #pragma unroll
        for (int r = 0; r < 4; r++) {
            const int idx = r * 256 + tid;
            const int rr = idx >> 3;
            const int c4 = idx & 7;
            ra[r] = *(const float4*)(A + (size_t)(m0 + rr) * K + (k0 + c4 * 4));
            rw[r] = *(const float4*)(W + (size_t)(n0 + rr) * K + (k0 + c4 * 4));
        }
    };
    auto storebuf = [&](int b) {
        __half* buf = smem + b * BUF_H;
        #pragma unroll
        for (int r = 0; r < 4; r++) {
            const int idx = r * 256 + tid;
            const int rr = idx >> 3;
            const int c4 = idx & 7;
            const int off = rr * LDT + c4 * 4;
            float4 v = ra[r];
            // A: hi only (truncation error ~2^-11 relative, within tolerance)
            __half a0 = __float2half_rn(v.x), a1 = __float2half_rn(v.y);
            __half a2 = __float2half_rn(v.z), a3 = __float2half_rn(v.w);
            *(uint2*)(buf + off) = make_uint2(pkh(a0, a1), pkh(a2, a3));
            v = rw[r];
            __half h0 = __float2half_rn(v.x), h1 = __float2half_rn(v.y);
            __half h2 = __float2half_rn(v.z), h3 = __float2half_rn(v.w);
            __half l0 = __float2half_rn(v.x - __half2float(h0));
            __half l1 = __float2half_rn(v.y - __half2float(h1));
            __half l2 = __float2half_rn(v.z - __half2float(h2));
            __half l3 = __float2half_rn(v.w - __half2float(h3));
            *(uint2*)(buf + 1 * TILE_H + off) = make_uint2(pkh(h0, h1), pkh(h2, h3));
            *(uint2*)(buf + 2 * TILE_H + off) = make_uint2(pkh(l0, l1), pkh(l2, l3));
        }
    };

    const int a_row    = wm + (lane & 15);
    const int a_colsel = (lane >> 4) << 3;
    const int b_rowsel = ((lane >> 4) & 1) * 8 + (lane & 7);
    const int b_colsel = ((lane >> 3) & 1) * 8;

    auto compute = [&](int b) {
        const uint32_t base = smem_u32(smem + b * BUF_H);
        #pragma unroll
        for (int ks = 0; ks < 2; ks++) {
            const int kb = ks * 16;
            uint32_t ah[2][4], bh[8][2], bl[8][2];
            #pragma unroll
            for (int i = 0; i < 2; i++) {
                const uint32_t off = ((a_row + i * 16) * LDT + kb + a_colsel) * 2;
                ldsm4(ah[i], base + off);
            }
            #pragma unroll
            for (int p = 0; p < 4; p++) {
                const int nrow = wn + p * 16 + b_rowsel;
                const uint32_t off = (nrow * LDT + kb + b_colsel) * 2;
                uint32_t t[4];
                ldsm4(t, base + 1 * TILE_B + off);
                bh[2 * p][0] = t[0]; bh[2 * p][1] = t[1];
                bh[2 * p + 1][0] = t[2]; bh[2 * p + 1][1] = t[3];
                ldsm4(t, base + 2 * TILE_B + off);
                bl[2 * p][0] = t[0]; bl[2 * p][1] = t[1];
                bl[2 * p + 1][0] = t[2]; bl[2 * p + 1][1] = t[3];
            }
            #pragma unroll
            for (int i = 0; i < 2; i++)
                #pragma unroll
                for (int j = 0; j < 8; j++) mma16816(acc[i][j], ah[i], bh[j]);
            #pragma unroll
            for (int i = 0; i < 2; i++)
                #pragma unroll
                for (int j = 0; j < 8; j++) mma16816(acc[i][j], ah[i], bl[j]);
        }
    };

    stage(0);
    storebuf(0);
    __syncthreads();

    for (int ch = 0; ch < nch; ch++) {
        if (ch + 1 < nch) stage((ch + 1) * BK);
        compute(ch & 1);
        __syncthreads();
        if (ch + 1 < nch) storebuf((ch + 1) & 1);
        __syncthreads();
    }

    // ---- epilogue ----
    #pragma unroll
    for (int i = 0; i < 2; i++) {
        const int row = m0 + wm + i * 16 + (lane >> 2);
        #pragma unroll
        for (int j = 0; j < 8; j++) {
            const int col = n0 + wn + j * 8 + (lane & 3) * 2;
            const float b0 = bias[col], b1 = bias[col + 1];
            #pragma unroll
            for (int half_ = 0; half_ < 2; half_++) {
                const int r = row + half_ * 8;
                float v0 = acc[i][j][half_ * 2 + 0] + b0;
                float v1 = acc[i][j][half_ * 2 + 1] + b1;
                if (EPI == 1) { v0 = gelu_tanh(v0); v1 = gelu_tanh(v1); }
                const size_t off = (size_t)r * N + col;
                if (EPI == 2) {
                    float2 r1 = *(const float2*)(res1 + off);
                    float2 r2 = *(const float2*)(res2 + off);
                    v0 += r1.x + r2.x; v1 += r1.y + r2.y;
                }
                *(float2*)(C + off) = make_float2(v0, v1);
            }
        }
    }
}

// ---------------- LayerNorm ----------------
__global__ void ln_kernel(const float* __restrict__ x,
                          const float* __restrict__ w,
                          const float* __restrict__ b,
                          float* __restrict__ out)
{
    const int s = blockIdx.x;
    const int tid = threadIdx.x;
    const float* row = x + (size_t)s * DIM;
    float sum = 0.f, sumsq = 0.f;
    for (int i = tid; i < DIM; i += 256) {
        float v = row[i];
        sum += v; sumsq += v * v;
    }
    __shared__ float r1[256], r2[256];
    r1[tid] = sum; r2[tid] = sumsq;
    __syncthreads();
    for (int st = 128; st > 0; st >>= 1) {
        if (tid < st) { r1[tid] += r1[tid + st]; r2[tid] += r2[tid + st]; }
        __syncthreads();
    }
    const float mu  = r1[0] * (1.f / DIM);
    const float var = r2[0] * (1.f / DIM) - mu * mu;
    const float rstd = rsqrtf(var + EPS);
    float* orow = out + (size_t)s * DIM;
    for (int i = tid; i < DIM; i += 256)
        orow[i] = (row[i] - mu) * rstd * w[i] + b[i];
}

// ---------------- split QKV + RoPE ----------------
__global__ void prep_qkv_kernel(const float* __restrict__ qkv,
                                const int* __restrict__ input_pos)
{
    const int s = blockIdx.x;
    const float pos = (float)input_pos[s];
    const float* row = qkv + (size_t)s * (3 * DIM);
    for (int idx = threadIdx.x; idx < DIM; idx += 256) {
        const int h = idx / HEAD_DIM;
        const int d = idx - h * HEAD_DIM;
        const size_t dsti = ((size_t)h * S_LEN + s) * HEAD_DIM + d;

        float qv = row[idx];
        float kv = row[DIM + idx];
        float vv = row[2 * DIM + idx];

        if (d < ROT_DIM) {
            const int i = (d < 16) ? d : d - 16;
            const float inv = __powf(10000.f, -(float)i / 16.f);
            const float ang = pos * inv;
            const float c = __cosf(ang), sn = __sinf(ang);
            if (d < 16) {
                float q2 = row[idx + 16];
                float k2 = row[DIM + idx + 16];
                qv = qv * c - q2 * sn;
                kv = kv * c - k2 * sn;
            } else {
                float q2 = row[idx - 16];
                float k2 = row[DIM + idx - 16];
                qv = qv * c + q2 * sn;
                kv = kv * c + k2 * sn;
            }
        }
        g_q[dsti] = qv;
        g_k[dsti] = kv;
        g_v[dsti] = vv;
    }
}

// ---------------- flash-style causal attention ----------------
#define BQ 64
#define BKV 32

__global__ __launch_bounds__(256)
void attn_kernel(float* __restrict__ y)
{
    __shared__ float sq[BQ][HEAD_DIM + 1];
    __shared__ float skv[BKV][HEAD_DIM + 1];
    __shared__ float ss[BQ][BKV + 1];

    const int qb = blockIdx.x;
    const int h  = blockIdx.y;
    const int tid = threadIdx.x;
    const int r   = tid & 63;
    const int grp = tid >> 6;
    const int j0  = grp * 8;
    const int d0  = grp * 20;
    const int qi  = qb * BQ + r;
    const float scale = 0.11180339887498949f;

    {
        const float* qg = g_q + ((size_t)h * S_LEN + qb * BQ) * HEAD_DIM;
        for (int i = tid; i < BQ * HEAD_DIM; i += 256)
            sq[i / HEAD_DIM][i % HEAD_DIM] = qg[i];
    }
    __syncthreads();

    float o[20];
    #pragma unroll
    for (int d = 0; d < 20; d++) o[d] = 0.f;
    float m = -INFINITY, l = 0.f;

    const int kb_max = (qb * BQ + BQ - 1) / BKV;
    for (int kb = 0; kb <= kb_max; kb++) {
        const float* kg = g_k + ((size_t)h * S_LEN + kb * BKV) * HEAD_DIM;
        for (int i = tid; i < BKV * HEAD_DIM; i += 256)
            skv[i / HEAD_DIM][i % HEAD_DIM] = kg[i];
        __syncthreads();

        #pragma unroll
        for (int jj = 0; jj < 8; jj++) {
            const int j = j0 + jj;
            const int ki = kb * BKV + j;
            float dot = 0.f;
            #pragma unroll
            for (int dd = 0; dd < HEAD_DIM; dd++)
                dot = fmaf(sq[r][dd], skv[j][dd], dot);
            ss[r][j] = (ki <= qi) ? dot * scale : -1e9f;
        }
        __syncthreads();

        const float* vg = g_v + ((size_t)h * S_LEN + kb * BKV) * HEAD_DIM;
        for (int i = tid; i < BKV * HEAD_DIM; i += 256)
            skv[i / HEAD_DIM][i % HEAD_DIM] = vg[i];
        __syncthreads();

        float mt = -INFINITY;
        #pragma unroll
        for (int j = 0; j < BKV; j++) mt = fmaxf(mt, ss[r][j]);
        const float mnew = fmaxf(m, mt);
        const float alpha = __expf(m - mnew);
        l *= alpha;
        #pragma unroll
        for (int d = 0; d < 20; d++) o[d] *= alpha;
        #pragma unroll
        for (int j = 0; j < BKV; j++) {
            const float p = __expf(ss[r][j] - mnew);
            l += p * 0.25f;
            #pragma unroll
            for (int d = 0; d < 20; d++)
                o[d] = fmaf(p, skv[j][d0 + d], o[d]);
        }
        m = mnew;
        __syncthreads();
    }

    const float inv_l = 1.f / (4.f * l);
    float* yout = y + (size_t)qi * DIM + h * HEAD_DIM + d0;
    #pragma unroll
    for (int d = 0; d < 20; d++) yout[d] = o[d] * inv_l;
}

// ---------------- host launch ----------------
extern "C" void kernel_launch(void* const* d_in, const int* in_sizes, int n_in,
                              void* d_out, int out_size)
{
    const float* x       = (const float*)d_in[0];
    const int*   pos     = (const int*)  d_in[1];
    const float* ln_w    = (const float*)d_in[3];
    const float* ln_b    = (const float*)d_in[4];
    const float* wqkv_w  = (const float*)d_in[5];
    const float* wqkv_b  = (const float*)d_in[6];
    const float* wo_w    = (const float*)d_in[7];
    const float* wo_b    = (const float*)d_in[8];
    const float* w1_w    = (const float*)d_in[9];
    const float* w1_b    = (const float*)d_in[10];
    const float* w2_w    = (const float*)d_in[11];
    const float* w2_b    = (const float*)d_in[12];
    float* out = (float*)d_out;

    float *h_p, *qkv_p, *y_p, *attn_p, *ffn1_p;
    cudaGetSymbolAddress((void**)&h_p,    g_h);
    cudaGetSymbolAddress((void**)&qkv_p,  g_qkv);
    cudaGetSymbolAddress((void**)&y_p,    g_y);
    cudaGetSymbolAddress((void**)&attn_p, g_attn);
    cudaGetSymbolAddress((void**)&ffn1_p, g_ffn1);

    cudaFuncSetAttribute(mma_gemm<0>, cudaFuncAttributeMaxDynamicSharedMemorySize, SMEM_DYN);
    cudaFuncSetAttribute(mma_gemm<1>, cudaFuncAttributeMaxDynamicSharedMemorySize, SMEM_DYN);
    cudaFuncSetAttribute(mma_gemm<2>, cudaFuncAttributeMaxDynamicSharedMemorySize, SMEM_DYN);

    // 1. LayerNorm
    ln_kernel<<<S_LEN, 256>>>(x, ln_w, ln_b, h_p);

    // 2. QKV projection
    mma_gemm<0><<<dim3(S_LEN / 128, 3 * DIM / 128), 256, SMEM_DYN>>>(
        h_p, wqkv_w, wqkv_b, qkv_p, S_LEN, 3 * DIM, DIM, nullptr, nullptr);

    // 3. split + RoPE
    prep_qkv_kernel<<<S_LEN, 256>>>(qkv_p, pos);

    // 4. attention
    attn_kernel<<<dim3(S_LEN / BQ, N_HEAD), 256>>>(y_p);

    // 5. output projection
    mma_gemm<0><<<dim3(S_LEN / 128, DIM / 128), 256, SMEM_DYN>>>(
        y_p, wo_w, wo_b, attn_p, S_LEN, DIM, DIM, nullptr, nullptr);

    // 6. FFN up + gelu
    mma_gemm<1><<<dim3(S_LEN / 128, INTER / 128), 256, SMEM_DYN>>>(
        h_p, w1_w, w1_b, ffn1_p, S_LEN, INTER, DIM, nullptr, nullptr);

    // 7. FFN down + residual fuse
    mma_gemm<2><<<dim3(S_LEN / 128, DIM / 128), 256, SMEM_DYN>>>(
        ffn1_p, w2_w, w2_b, out, S_LEN, DIM, INTER, attn_p, x);
}

// round 14
// speedup vs baseline: 3.3420x; 1.4036x over previous
#include <cuda_runtime.h>
#include <cuda_fp16.h>
#include <math.h>
#include <stdint.h>

#define S_LEN 2048
#define DIM 2560
#define N_HEAD 32
#define HEAD_DIM 80
#define ROT_DIM 32
#define INTER 10240
#define EPS 1e-5f

// ---------------- scratch ----------------
__device__ float g_h   [S_LEN * DIM];
__device__ float g_qkv [S_LEN * 3 * DIM];
__device__ float g_y   [S_LEN * DIM];
__device__ float g_attn[S_LEN * DIM];
__device__ float g_ffn1[S_LEN * INTER];
__device__ __half g_qh [N_HEAD * S_LEN * HEAD_DIM];
__device__ __half g_kh [N_HEAD * S_LEN * HEAD_DIM];
__device__ __half g_vh [N_HEAD * S_LEN * HEAD_DIM];

// ---------------- helpers ----------------
__device__ __forceinline__ uint32_t smem_u32(const void* p) {
    uint32_t a;
    asm("{ .reg .u64 t; cvta.to.shared.u64 t, %1; cvt.u32.u64 %0, t; }" : "=r"(a) : "l"(p));
    return a;
}
__device__ __forceinline__ uint32_t pkh(__half a, __half b) {
    __half2 t = __halves2half2(a, b);
    return *(uint32_t*)&t;
}
__device__ __forceinline__ uint32_t pkf(float a, float b) {
    return pkh(__float2half_rn(a), __float2half_rn(b));
}
__device__ __forceinline__ void ldsm4(uint32_t r[4], uint32_t addr) {
    asm volatile("ldmatrix.sync.aligned.m8n8.x4.shared.b16 {%0,%1,%2,%3}, [%4];"
                 : "=r"(r[0]), "=r"(r[1]), "=r"(r[2]), "=r"(r[3]) : "r"(addr));
}
__device__ __forceinline__ void ldsm4t(uint32_t r[4], uint32_t addr) {
    asm volatile("ldmatrix.sync.aligned.m8n8.x4.trans.shared.b16 {%0,%1,%2,%3}, [%4];"
                 : "=r"(r[0]), "=r"(r[1]), "=r"(r[2]), "=r"(r[3]) : "r"(addr));
}
__device__ __forceinline__ void mma16816(float c[4], const uint32_t a[4], const uint32_t b[2]) {
    asm volatile("mma.sync.aligned.m16n8k16.row.col.f32.f16.f16.f32 "
                 "{%0,%1,%2,%3}, {%4,%5,%6,%7}, {%8,%9}, {%0,%1,%2,%3};"
                 : "+f"(c[0]), "+f"(c[1]), "+f"(c[2]), "+f"(c[3])
                 : "r"(a[0]), "r"(a[1]), "r"(a[2]), "r"(a[3]), "r"(b[0]), "r"(b[1]));
}
__device__ __forceinline__ float gelu_tanh(float v) {
    float c = v + 0.044715f * v * v * v;
    return 0.5f * v * (1.f + tanhf(0.7978845608028654f * c));
}

// ---------------- mma.sync fp16x2 GEMM (round-13 winner, unchanged) ----------------
#define BK 32
#define LDT 40
#define TILE_H (128 * LDT)
#define TILE_B (TILE_H * 2)
#define BUF_H  (3 * TILE_H)
#define BUF_B  (3 * TILE_B)
#define SMEM_DYN (2 * BUF_B)

template<int EPI>
__global__ __launch_bounds__(256)
void mma_gemm(const float* __restrict__ A, const float* __restrict__ W,
              const float* __restrict__ bias, float* __restrict__ C,
              int M, int N, int K,
              const float* __restrict__ res1, const float* __restrict__ res2)
{
    extern __shared__ __align__(16) __half smem[];
    const int tid  = threadIdx.x;
    const int lane = tid & 31;
    const int wid  = tid >> 5;
    const int wm   = (wid & 3) * 32;
    const int wn   = (wid >> 2) * 64;
    const int m0 = blockIdx.x * 128;
    const int n0 = blockIdx.y * 128;

    float acc[2][8][4];
    #pragma unroll
    for (int i = 0; i < 2; i++)
        #pragma unroll
        for (int j = 0; j < 8; j++)
            #pragma unroll
            for (int q = 0; q < 4; q++) acc[i][j][q] = 0.f;

    const int nch = K / BK;
    float4 ra[4], rw[4];

    auto stage = [&](int k0) {
        #pragma unroll
        for (int r = 0; r < 4; r++) {
            const int idx = r * 256 + tid;
            const int rr = idx >> 3;
            const int c4 = idx & 7;
            ra[r] = *(const float4*)(A + (size_t)(m0 + rr) * K + (k0 + c4 * 4));
            rw[r] = *(const float4*)(W + (size_t)(n0 + rr) * K + (k0 + c4 * 4));
        }
    };
    auto storebuf = [&](int b) {
        __half* buf = smem + b * BUF_H;
        #pragma unroll
        for (int r = 0; r < 4; r++) {
            const int idx = r * 256 + tid;
            const int rr = idx >> 3;
            const int c4 = idx & 7;
            const int off = rr * LDT + c4 * 4;
            float4 v = ra[r];
            *(uint2*)(buf + off) = make_uint2(pkf(v.x, v.y), pkf(v.z, v.w));
            v = rw[r];
            __half h0 = __float2half_rn(v.x), h1 = __float2half_rn(v.y);
            __half h2 = __float2half_rn(v.z), h3 = __float2half_rn(v.w);
            __half l0 = __float2half_rn(v.x - __half2float(h0));
            __half l1 = __float2half_rn(v.y - __half2float(h1));
            __half l2 = __float2half_rn(v.z - __half2float(h2));
            __half l3 = __float2half_rn(v.w - __half2float(h3));
            *(uint2*)(buf + 1 * TILE_H + off) = make_uint2(pkh(h0, h1), pkh(h2, h3));
            *(uint2*)(buf + 2 * TILE_H + off) = make_uint2(pkh(l0, l1), pkh(l2, l3));
        }
    };

    const int a_row    = wm + (lane & 15);
    const int a_colsel = (lane >> 4) << 3;
    const int b_rowsel = ((lane >> 4) & 1) * 8 + (lane & 7);
    const int b_colsel = ((lane >> 3) & 1) * 8;

    auto compute = [&](int b) {
        const uint32_t base = smem_u32(smem + b * BUF_H);
        #pragma unroll
        for (int ks = 0; ks < 2; ks++) {
            const int kb = ks * 16;
            uint32_t ah[2][4], bh[8][2], bl[8][2];
            #pragma unroll
            for (int i = 0; i < 2; i++) {
                const uint32_t off = ((a_row + i * 16) * LDT + kb + a_colsel) * 2;
                ldsm4(ah[i], base + off);
            }
            #pragma unroll
            for (int p = 0; p < 4; p++) {
                const int nrow = wn + p * 16 + b_rowsel;
                const uint32_t off = (nrow * LDT + kb + b_colsel) * 2;
                uint32_t t[4];
                ldsm4(t, base + 1 * TILE_B + off);
                bh[2 * p][0] = t[0]; bh[2 * p][1] = t[1];
                bh[2 * p + 1][0] = t[2]; bh[2 * p + 1][1] = t[3];
                ldsm4(t, base + 2 * TILE_B + off);
                bl[2 * p][0] = t[0]; bl[2 * p][1] = t[1];
                bl[2 * p + 1][0] = t[2]; bl[2 * p + 1][1] = t[3];
            }
            #pragma unroll
            for (int i = 0; i < 2; i++)
                #pragma unroll
                for (int j = 0; j < 8; j++) mma16816(acc[i][j], ah[i], bh[j]);
            #pragma unroll
            for (int i = 0; i < 2; i++)
                #pragma unroll
                for (int j = 0; j < 8; j++) mma16816(acc[i][j], ah[i], bl[j]);
        }
    };

    stage(0);
    storebuf(0);
    __syncthreads();

    for (int ch = 0; ch < nch; ch++) {
        if (ch + 1 < nch) stage((ch + 1) * BK);
        compute(ch & 1);
        __syncthreads();
        if (ch + 1 < nch) storebuf((ch + 1) & 1);
        __syncthreads();
    }

    #pragma unroll
    for (int i = 0; i < 2; i++) {
        const int row = m0 + wm + i * 16 + (lane >> 2);
        #pragma unroll
        for (int j = 0; j < 8; j++) {
            const int col = n0 + wn + j * 8 + (lane & 3) * 2;
            const float b0 = bias[col], b1 = bias[col + 1];
            #pragma unroll
            for (int half_ = 0; half_ < 2; half_++) {
                const int r = row + half_ * 8;
                float v0 = acc[i][j][half_ * 2 + 0] + b0;
                float v1 = acc[i][j][half_ * 2 + 1] + b1;
                if (EPI == 1) { v0 = gelu_tanh(v0); v1 = gelu_tanh(v1); }
                const size_t off = (size_t)r * N + col;
                if (EPI == 2) {
                    float2 r1 = *(const float2*)(res1 + off);
                    float2 r2 = *(const float2*)(res2 + off);
                    v0 += r1.x + r2.x; v1 += r1.y + r2.y;
                }
                *(float2*)(C + off) = make_float2(v0, v1);
            }
        }
    }
}

// ---------------- LayerNorm ----------------
__global__ void ln_kernel(const float* __restrict__ x,
                          const float* __restrict__ w,
                          const float* __restrict__ b,
                          float* __restrict__ out)
{
    const int s = blockIdx.x;
    const int tid = threadIdx.x;
    const float* row = x + (size_t)s * DIM;
    float sum = 0.f, sumsq = 0.f;
    for (int i = tid; i < DIM; i += 256) {
        float v = row[i];
        sum += v; sumsq += v * v;
    }
    __shared__ float r1[256], r2[256];
    r1[tid] = sum; r2[tid] = sumsq;
    __syncthreads();
    for (int st = 128; st > 0; st >>= 1) {
        if (tid < st) { r1[tid] += r1[tid + st]; r2[tid] += r2[tid + st]; }
        __syncthreads();
    }
    const float mu  = r1[0] * (1.f / DIM);
    const float var = r2[0] * (1.f / DIM) - mu * mu;
    const float rstd = rsqrtf(var + EPS);
    float* orow = out + (size_t)s * DIM;
    for (int i = tid; i < DIM; i += 256)
        orow[i] = (row[i] - mu) * rstd * w[i] + b[i];
}

// ---------------- split QKV + RoPE -> fp16 head-major ----------------
__global__ void prep_qkv_kernel(const float* __restrict__ qkv,
                                const int* __restrict__ input_pos)
{
    const int s = blockIdx.x;
    const float pos = (float)input_pos[s];
    const float* row = qkv + (size_t)s * (3 * DIM);
    for (int idx = threadIdx.x; idx < DIM; idx += 256) {
        const int h = idx / HEAD_DIM;
        const int d = idx - h * HEAD_DIM;
        const size_t dsti = ((size_t)h * S_LEN + s) * HEAD_DIM + d;

        float qv = row[idx];
        float kv = row[DIM + idx];
        float vv = row[2 * DIM + idx];

        if (d < ROT_DIM) {
            const int i = (d < 16) ? d : d - 16;
            const float inv = __powf(10000.f, -(float)i / 16.f);
            const float ang = pos * inv;
            const float c = __cosf(ang), sn = __sinf(ang);
            if (d < 16) {
                float q2 = row[idx + 16];
                float k2 = row[DIM + idx + 16];
                qv = qv * c - q2 * sn;
                kv = kv * c - k2 * sn;
            } else {
                float q2 = row[idx - 16];
                float k2 = row[DIM + idx - 16];
                qv = qv * c + q2 * sn;
                kv = kv * c + k2 * sn;
            }
        }
        g_qh[dsti] = __float2half_rn(qv);
        g_kh[dsti] = __float2half_rn(kv);
        g_vh[dsti] = __float2half_rn(vv);
    }
}

// ---------------- tensor-core flash attention ----------------
// 128 threads / 4 warps; BQ=64 (16 rows per warp); BKV=64 per iteration.
#define LDQ 88   // padded halves per row (176B stride; conflict-free ldmatrix)

__global__ __launch_bounds__(128)
void attn_kernel(float* __restrict__ y)
{
    __shared__ __half sq[64 * LDQ];
    __shared__ __half sk[64 * LDQ];
    __shared__ __half sv[64 * LDQ];

    const int tid  = threadIdx.x;
    const int lane = tid & 31;
    const int warp = tid >> 5;
    const int qb = blockIdx.x;
    const int h  = blockIdx.y;
    const uint32_t sqb = smem_u32(sq);
    const uint32_t skb = smem_u32(sk);
    const uint32_t svb = smem_u32(sv);
    const float scale = 0.11180339887498949f;

    // load Q tile [64 x 80]
    {
        const __half* qg = g_qh + ((size_t)h * S_LEN + qb * 64) * HEAD_DIM;
        #pragma unroll
        for (int p = 0; p < 5; p++) {
            const int idx = p * 128 + tid;      // 0..639
            const int r = idx / 10, seg = idx % 10;
            *(uint4*)(sq + r * LDQ + seg * 8) = *(const uint4*)(qg + r * 80 + seg * 8);
        }
    }
    __syncthreads();

    // preload Q a-frags: 5 k-steps of 16
    uint32_t qa[5][4];
    {
        const uint32_t a_off = (uint32_t)((warp * 16 + (lane & 15)) * LDQ + ((lane >> 4) << 3)) * 2;
        #pragma unroll
        for (int ks = 0; ks < 5; ks++) ldsm4(qa[ks], sqb + a_off + ks * 32);
    }

    float o[10][4];
    #pragma unroll
    for (int j = 0; j < 10; j++)
        #pragma unroll
        for (int e = 0; e < 4; e++) o[j][e] = 0.f;
    float mr0 = -1e30f, mr1 = -1e30f, lr0 = 0.f, lr1 = 0.f;

    const int row0 = qb * 64 + warp * 16 + (lane >> 2);   // c-frag rows: row0, row0+8
    const uint32_t b_off = (uint32_t)(((((lane >> 4) & 1) * 8 + (lane & 7)) * LDQ) + ((lane >> 3) & 1) * 8) * 2;
    const uint32_t v_off = (uint32_t)((lane & 15) * LDQ + ((lane >> 4) << 3)) * 2;

    for (int kb = 0; kb <= qb; kb++) {
        // load K, V tiles [64 x 80]
        {
            const __half* kg = g_kh + ((size_t)h * S_LEN + kb * 64) * HEAD_DIM;
            const __half* vg = g_vh + ((size_t)h * S_LEN + kb * 64) * HEAD_DIM;
            #pragma unroll
            for (int p = 0; p < 5; p++) {
                const int idx = p * 128 + tid;
                const int r = idx / 10, seg = idx % 10;
                *(uint4*)(sk + r * LDQ + seg * 8) = *(const uint4*)(kg + r * 80 + seg * 8);
                *(uint4*)(sv + r * LDQ + seg * 8) = *(const uint4*)(vg + r * 80 + seg * 8);
            }
        }
        __syncthreads();

        // S = Q @ K^T  (8 key-blocks of n8)
        float s[8][4];
        #pragma unroll
        for (int j = 0; j < 8; j++)
            #pragma unroll
            for (int e = 0; e < 4; e++) s[j][e] = 0.f;
        #pragma unroll
        for (int ks = 0; ks < 5; ks++) {
            #pragma unroll
            for (int p = 0; p < 4; p++) {
                uint32_t t[4];
                ldsm4(t, skb + b_off + (uint32_t)(p * 16 * LDQ) * 2 + ks * 32);
                mma16816(s[2 * p],     qa[ks], t);
                mma16816(s[2 * p + 1], qa[ks], t + 2);
            }
        }

        // scale (+ causal mask on diagonal block only)
        if (kb == qb) {
            #pragma unroll
            for (int j = 0; j < 8; j++)
                #pragma unroll
                for (int e = 0; e < 4; e++) {
                    const int col = kb * 64 + j * 8 + (lane & 3) * 2 + (e & 1);
                    const int row = row0 + (e >> 1) * 8;
                    s[j][e] = (col <= row) ? s[j][e] * scale : -1e30f;
                }
        } else {
            #pragma unroll
            for (int j = 0; j < 8; j++)
                #pragma unroll
                for (int e = 0; e < 4; e++) s[j][e] *= scale;
        }

        // row max (quad shuffle over the 4 lanes covering the row)
        float m0 = -1e30f, m1 = -1e30f;
        #pragma unroll
        for (int j = 0; j < 8; j++) {
            m0 = fmaxf(m0, fmaxf(s[j][0], s[j][1]));
            m1 = fmaxf(m1, fmaxf(s[j][2], s[j][3]));
        }
        m0 = fmaxf(m0, __shfl_xor_sync(0xffffffffu, m0, 1));
        m0 = fmaxf(m0, __shfl_xor_sync(0xffffffffu, m0, 2));
        m1 = fmaxf(m1, __shfl_xor_sync(0xffffffffu, m1, 1));
        m1 = fmaxf(m1, __shfl_xor_sync(0xffffffffu, m1, 2));

        const float mn0 = fmaxf(mr0, m0), mn1 = fmaxf(mr1, m1);
        const float al0 = __expf(mr0 - mn0), al1 = __expf(mr1 - mn1);

        float lp0 = 0.f, lp1 = 0.f;
        #pragma unroll
        for (int j = 0; j < 8; j++) {
            s[j][0] = __expf(s[j][0] - mn0); lp0 += s[j][0];
            s[j][1] = __expf(s[j][1] - mn0); lp0 += s[j][1];
            s[j][2] = __expf(s[j][2] - mn1); lp1 += s[j][2];
            s[j][3] = __expf(s[j][3] - mn1); lp1 += s[j][3];
        }
        lp0 += __shfl_xor_sync(0xffffffffu, lp0, 1);
        lp0 += __shfl_xor_sync(0xffffffffu, lp0, 2);
        lp1 += __shfl_xor_sync(0xffffffffu, lp1, 1);
        lp1 += __shfl_xor_sync(0xffffffffu, lp1, 2);

        lr0 = lr0 * al0 + lp0;
        lr1 = lr1 * al1 + lp1;
        mr0 = mn0; mr1 = mn1;

        #pragma unroll
        for (int j = 0; j < 10; j++) {
            o[j][0] *= al0; o[j][1] *= al0;
            o[j][2] *= al1; o[j][3] *= al1;
        }

        // repack P (c-frags) -> A-frags for PV
        uint32_t pa[4][4];
        #pragma unroll
        for (int ks2 = 0; ks2 < 4; ks2++) {
            pa[ks2][0] = pkf(s[2 * ks2][0],     s[2 * ks2][1]);
            pa[ks2][1] = pkf(s[2 * ks2][2],     s[2 * ks2][3]);
            pa[ks2][2] = pkf(s[2 * ks2 + 1][0], s[2 * ks2 + 1][1]);
            pa[ks2][3] = pkf(s[2 * ks2 + 1][2], s[2 * ks2 + 1][3]);
        }

        // O += P @ V  (V via ldmatrix.trans; 5 dim-pairs of n8)
        #pragma unroll
        for (int ks2 = 0; ks2 < 4; ks2++) {
            #pragma unroll
            for (int np = 0; np < 5; np++) {
                uint32_t t[4];
                ldsm4t(t, svb + v_off + (uint32_t)(ks2 * 16 * LDQ) * 2 + np * 32);
                mma16816(o[2 * np],     pa[ks2], t);
                mma16816(o[2 * np + 1], pa[ks2], t + 2);
            }
        }

        __syncthreads();   // before overwriting sk/sv
    }

    const float il0 = 1.f / lr0, il1 = 1.f / lr1;
    #pragma unroll
    for (int j = 0; j < 10; j++) {
        const int col = h * HEAD_DIM + j * 8 + (lane & 3) * 2;
        *(float2*)(y + (size_t)row0 * DIM + col)       = make_float2(o[j][0] * il0, o[j][1] * il0);
        *(float2*)(y + (size_t)(row0 + 8) * DIM + col) = make_float2(o[j][2] * il1, o[j][3] * il1);
    }
}

// ---------------- host launch ----------------
extern "C" void kernel_launch(void* const* d_in, const int* in_sizes, int n_in,
                              void* d_out, int out_size)
{
    const float* x       = (const float*)d_in[0];
    const int*   pos     = (const int*)  d_in[1];
    const float* ln_w    = (const float*)d_in[3];
    const float* ln_b    = (const float*)d_in[4];
    const float* wqkv_w  = (const float*)d_in[5];
    const float* wqkv_b  = (const float*)d_in[6];
    const float* wo_w    = (const float*)d_in[7];
    const float* wo_b    = (const float*)d_in[8];
    const float* w1_w    = (const float*)d_in[9];
    const float* w1_b    = (const float*)d_in[10];
    const float* w2_w    = (const float*)d_in[11];
    const float* w2_b    = (const float*)d_in[12];
    float* out = (float*)d_out;

    float *h_p, *qkv_p, *y_p, *attn_p, *ffn1_p;
    cudaGetSymbolAddress((void**)&h_p,    g_h);
    cudaGetSymbolAddress((void**)&qkv_p,  g_qkv);
    cudaGetSymbolAddress((void**)&y_p,    g_y);
    cudaGetSymbolAddress((void**)&attn_p, g_attn);
    cudaGetSymbolAddress((void**)&ffn1_p, g_ffn1);

    cudaFuncSetAttribute(mma_gemm<0>, cudaFuncAttributeMaxDynamicSharedMemorySize, SMEM_DYN);
    cudaFuncSetAttribute(mma_gemm<1>, cudaFuncAttributeMaxDynamicSharedMemorySize, SMEM_DYN);
    cudaFuncSetAttribute(mma_gemm<2>, cudaFuncAttributeMaxDynamicSharedMemorySize, SMEM_DYN);

    // 1. LayerNorm
    ln_kernel<<<S_LEN, 256>>>(x, ln_w, ln_b, h_p);

    // 2. QKV projection
    mma_gemm<0><<<dim3(S_LEN / 128, 3 * DIM / 128), 256, SMEM_DYN>>>(
        h_p, wqkv_w, wqkv_b, qkv_p, S_LEN, 3 * DIM, DIM, nullptr, nullptr);

    // 3. split + RoPE -> fp16
    prep_qkv_kernel<<<S_LEN, 256>>>(qkv_p, pos);

    // 4. tensor-core flash attention
    attn_kernel<<<dim3(S_LEN / 64, N_HEAD), 128>>>(y_p);

    // 5. output projection
    mma_gemm<0><<<dim3(S_LEN / 128, DIM / 128), 256, SMEM_DYN>>>(
        y_p, wo_w, wo_b, attn_p, S_LEN, DIM, DIM, nullptr, nullptr);

    // 6. FFN up + gelu
    mma_gemm<1><<<dim3(S_LEN / 128, INTER / 128), 256, SMEM_DYN>>>(
        h_p, w1_w, w1_b, ffn1_p, S_LEN, INTER, DIM, nullptr, nullptr);

    // 7. FFN down + residual fuse
    mma_gemm<2><<<dim3(S_LEN / 128, DIM / 128), 256, SMEM_DYN>>>(
        ffn1_p, w2_w, w2_b, out, S_LEN, DIM, INTER, attn_p, x);
}

// round 15
// speedup vs baseline: 3.9196x; 1.1728x over previous
#include <cuda_runtime.h>
#include <cuda_fp16.h>
#include <math.h>
#include <stdint.h>

#define S_LEN 2048
#define DIM 2560
#define N_HEAD 32
#define HEAD_DIM 80
#define ROT_DIM 32
#define INTER 10240
#define EPS 1e-5f

// ---------------- scratch ----------------
__device__ __half g_h   [S_LEN * DIM];            // post-LN, fp16
__device__ float  g_qkv [S_LEN * 3 * DIM];
__device__ __half g_y   [S_LEN * DIM];            // attention out, fp16
__device__ float  g_attn[S_LEN * DIM];
__device__ __half g_ffn1[S_LEN * INTER];          // gelu(ffn1), fp16
__device__ __half g_qh [N_HEAD * S_LEN * HEAD_DIM];
__device__ __half g_kh [N_HEAD * S_LEN * HEAD_DIM];
__device__ __half g_vh [N_HEAD * S_LEN * HEAD_DIM];

// ---------------- helpers ----------------
__device__ __forceinline__ uint32_t smem_u32(const void* p) {
    uint32_t a;
    asm("{ .reg .u64 t; cvta.to.shared.u64 t, %1; cvt.u32.u64 %0, t; }" : "=r"(a) : "l"(p));
    return a;
}
__device__ __forceinline__ uint32_t pkh(__half a, __half b) {
    __half2 t = __halves2half2(a, b);
    return *(uint32_t*)&t;
}
__device__ __forceinline__ uint32_t pkf(float a, float b) {
    return pkh(__float2half_rn(a), __float2half_rn(b));
}
__device__ __forceinline__ void ldsm4(uint32_t r[4], uint32_t addr) {
    asm volatile("ldmatrix.sync.aligned.m8n8.x4.shared.b16 {%0,%1,%2,%3}, [%4];"
                 : "=r"(r[0]), "=r"(r[1]), "=r"(r[2]), "=r"(r[3]) : "r"(addr));
}
__device__ __forceinline__ void ldsm4t(uint32_t r[4], uint32_t addr) {
    asm volatile("ldmatrix.sync.aligned.m8n8.x4.trans.shared.b16 {%0,%1,%2,%3}, [%4];"
                 : "=r"(r[0]), "=r"(r[1]), "=r"(r[2]), "=r"(r[3]) : "r"(addr));
}
__device__ __forceinline__ void mma16816(float c[4], const uint32_t a[4], const uint32_t b[2]) {
    asm volatile("mma.sync.aligned.m16n8k16.row.col.f32.f16.f16.f32 "
                 "{%0,%1,%2,%3}, {%4,%5,%6,%7}, {%8,%9}, {%0,%1,%2,%3};"
                 : "+f"(c[0]), "+f"(c[1]), "+f"(c[2]), "+f"(c[3])
                 : "r"(a[0]), "r"(a[1]), "r"(a[2]), "r"(a[3]), "r"(b[0]), "r"(b[1]));
}
__device__ __forceinline__ float gelu_tanh(float v) {
    float c = v + 0.044715f * v * v * v;
    return 0.5f * v * (1.f + tanhf(0.7978845608028654f * c));
}

// ---------------- mma.sync fp16x2 GEMM: C = A(fp16) @ W(fp32->hi/lo)^T + bias ----------------
#define BK 32
#define LDT 40
#define TILE_H (128 * LDT)
#define TILE_B (TILE_H * 2)
#define BUF_H  (3 * TILE_H)
#define BUF_B  (3 * TILE_B)
#define SMEM_DYN (2 * BUF_B)

// EPI: 0 -> fp32 C; 1 -> gelu -> fp16 Ch; 2 -> fp32 C + res1 + res2
template<int EPI>
__global__ __launch_bounds__(256)
void mma_gemm(const __half* __restrict__ A, const float* __restrict__ W,
              const float* __restrict__ bias,
              float* __restrict__ C, __half* __restrict__ Ch,
              int M, int N, int K,
              const float* __restrict__ res1, const float* __restrict__ res2)
{
    extern __shared__ __align__(16) __half smem[];
    const int tid  = threadIdx.x;
    const int lane = tid & 31;
    const int wid  = tid >> 5;
    const int wm   = (wid & 3) * 32;
    const int wn   = (wid >> 2) * 64;
    const int m0 = blockIdx.x * 128;
    const int n0 = blockIdx.y * 128;

    float acc[2][8][4];
    #pragma unroll
    for (int i = 0; i < 2; i++)
        #pragma unroll
        for (int j = 0; j < 8; j++)
            #pragma unroll
            for (int q = 0; q < 4; q++) acc[i][j][q] = 0.f;

    const int nch = K / BK;
    uint4  ua[2];    // A: 128x32 fp16 = 8KB = 512x16B, 2 reps
    float4 rw[4];    // W: 128x32 fp32 = 16KB, 4 reps

    auto stage = [&](int k0) {
        #pragma unroll
        for (int r = 0; r < 2; r++) {
            const int idx = r * 256 + tid;         // 0..511
            const int rr = idx >> 2, seg = idx & 3;
            ua[r] = *(const uint4*)(A + (size_t)(m0 + rr) * K + k0 + seg * 8);
        }
        #pragma unroll
        for (int r = 0; r < 4; r++) {
            const int idx = r * 256 + tid;
            const int rr = idx >> 3, c4 = idx & 7;
            rw[r] = *(const float4*)(W + (size_t)(n0 + rr) * K + k0 + c4 * 4);
        }
    };
    auto storebuf = [&](int b) {
        __half* buf = smem + b * BUF_H;
        #pragma unroll
        for (int r = 0; r < 2; r++) {
            const int idx = r * 256 + tid;
            const int rr = idx >> 2, seg = idx & 3;
            *(uint4*)(buf + rr * LDT + seg * 8) = ua[r];      // no conversion
        }
        #pragma unroll
        for (int r = 0; r < 4; r++) {
            const int idx = r * 256 + tid;
            const int rr = idx >> 3, c4 = idx & 7;
            const int off = rr * LDT + c4 * 4;
            float4 v = rw[r];
            __half h0 = __float2half_rn(v.x), h1 = __float2half_rn(v.y);
            __half h2 = __float2half_rn(v.z), h3 = __float2half_rn(v.w);
            __half l0 = __float2half_rn(v.x - __half2float(h0));
            __half l1 = __float2half_rn(v.y - __half2float(h1));
            __half l2 = __float2half_rn(v.z - __half2float(h2));
            __half l3 = __float2half_rn(v.w - __half2float(h3));
            *(uint2*)(buf + 1 * TILE_H + off) = make_uint2(pkh(h0, h1), pkh(h2, h3));
            *(uint2*)(buf + 2 * TILE_H + off) = make_uint2(pkh(l0, l1), pkh(l2, l3));
        }
    };

    const int a_row    = wm + (lane & 15);
    const int a_colsel = (lane >> 4) << 3;
    const int b_rowsel = ((lane >> 4) & 1) * 8 + (lane & 7);
    const int b_colsel = ((lane >> 3) & 1) * 8;

    auto compute = [&](int b) {
        const uint32_t base = smem_u32(smem + b * BUF_H);
        #pragma unroll
        for (int ks = 0; ks < 2; ks++) {
            const int kb = ks * 16;
            uint32_t ah[2][4], bh[8][2], bl[8][2];
            #pragma unroll
            for (int i = 0; i < 2; i++) {
                const uint32_t off = ((a_row + i * 16) * LDT + kb + a_colsel) * 2;
                ldsm4(ah[i], base + off);
            }
            #pragma unroll
            for (int p = 0; p < 4; p++) {
                const int nrow = wn + p * 16 + b_rowsel;
                const uint32_t off = (nrow * LDT + kb + b_colsel) * 2;
                uint32_t t[4];
                ldsm4(t, base + 1 * TILE_B + off);
                bh[2 * p][0] = t[0]; bh[2 * p][1] = t[1];
                bh[2 * p + 1][0] = t[2]; bh[2 * p + 1][1] = t[3];
                ldsm4(t, base + 2 * TILE_B + off);
                bl[2 * p][0] = t[0]; bl[2 * p][1] = t[1];
                bl[2 * p + 1][0] = t[2]; bl[2 * p + 1][1] = t[3];
            }
            #pragma unroll
            for (int i = 0; i < 2; i++)
                #pragma unroll
                for (int j = 0; j < 8; j++) mma16816(acc[i][j], ah[i], bh[j]);
            #pragma unroll
            for (int i = 0; i < 2; i++)
                #pragma unroll
                for (int j = 0; j < 8; j++) mma16816(acc[i][j], ah[i], bl[j]);
        }
    };

    stage(0);
    storebuf(0);
    __syncthreads();

    for (int ch = 0; ch < nch; ch++) {
        if (ch + 1 < nch) stage((ch + 1) * BK);
        compute(ch & 1);
        // NOTE: no barrier here — storebuf targets the opposite buffer, whose
        // last readers were fenced by the __syncthreads below in iter ch-1.
        if (ch + 1 < nch) storebuf((ch + 1) & 1);
        __syncthreads();
    }

    // ---- epilogue ----
    #pragma unroll
    for (int i = 0; i < 2; i++) {
        const int row = m0 + wm + i * 16 + (lane >> 2);
        #pragma unroll
        for (int j = 0; j < 8; j++) {
            const int col = n0 + wn + j * 8 + (lane & 3) * 2;
            const float b0 = bias[col], b1 = bias[col + 1];
            #pragma unroll
            for (int half_ = 0; half_ < 2; half_++) {
                const int r = row + half_ * 8;
                float v0 = acc[i][j][half_ * 2 + 0] + b0;
                float v1 = acc[i][j][half_ * 2 + 1] + b1;
                const size_t off = (size_t)r * N + col;
                if (EPI == 1) {
                    v0 = gelu_tanh(v0); v1 = gelu_tanh(v1);
                    *(uint32_t*)(Ch + off) = pkf(v0, v1);
                } else {
                    if (EPI == 2) {
                        float2 r1 = *(const float2*)(res1 + off);
                        float2 r2 = *(const float2*)(res2 + off);
                        v0 += r1.x + r2.x; v1 += r1.y + r2.y;
                    }
                    *(float2*)(C + off) = make_float2(v0, v1);
                }
            }
        }
    }
}

// ---------------- LayerNorm -> fp16 ----------------
__global__ void ln_kernel(const float* __restrict__ x,
                          const float* __restrict__ w,
                          const float* __restrict__ b)
{
    const int s = blockIdx.x;
    const int tid = threadIdx.x;
    const float* row = x + (size_t)s * DIM;
    float sum = 0.f, sumsq = 0.f;
    for (int i = tid; i < DIM; i += 256) {
        float v = row[i];
        sum += v; sumsq += v * v;
    }
    __shared__ float r1[256], r2[256];
    r1[tid] = sum; r2[tid] = sumsq;
    __syncthreads();
    for (int st = 128; st > 0; st >>= 1) {
        if (tid < st) { r1[tid] += r1[tid + st]; r2[tid] += r2[tid + st]; }
        __syncthreads();
    }
    const float mu  = r1[0] * (1.f / DIM);
    const float var = r2[0] * (1.f / DIM) - mu * mu;
    const float rstd = rsqrtf(var + EPS);
    for (int i = tid; i < DIM; i += 256)
        g_h[(size_t)s * DIM + i] = __float2half_rn((row[i] - mu) * rstd * w[i] + b[i]);
}

// ---------------- split QKV + RoPE -> fp16 head-major ----------------
__global__ void prep_qkv_kernel(const float* __restrict__ qkv,
                                const int* __restrict__ input_pos)
{
    const int s = blockIdx.x;
    const float pos = (float)input_pos[s];
    const float* row = qkv + (size_t)s * (3 * DIM);
    for (int idx = threadIdx.x; idx < DIM; idx += 256) {
        const int h = idx / HEAD_DIM;
        const int d = idx - h * HEAD_DIM;
        const size_t dsti = ((size_t)h * S_LEN + s) * HEAD_DIM + d;

        float qv = row[idx];
        float kv = row[DIM + idx];
        float vv = row[2 * DIM + idx];

        if (d < ROT_DIM) {
            const int i = (d < 16) ? d : d - 16;
            const float inv = __powf(10000.f, -(float)i / 16.f);
            const float ang = pos * inv;
            const float c = __cosf(ang), sn = __sinf(ang);
            if (d < 16) {
                float q2 = row[idx + 16];
                float k2 = row[DIM + idx + 16];
                qv = qv * c - q2 * sn;
                kv = kv * c - k2 * sn;
            } else {
                float q2 = row[idx - 16];
                float k2 = row[DIM + idx - 16];
                qv = qv * c + q2 * sn;
                kv = kv * c + k2 * sn;
            }
        }
        g_qh[dsti] = __float2half_rn(qv);
        g_kh[dsti] = __float2half_rn(kv);
        g_vh[dsti] = __float2half_rn(vv);
    }
}

// ---------------- tensor-core flash attention (round-14 winner; fp16 y out) ----------------
#define LDQ 88

__global__ __launch_bounds__(128)
void attn_kernel(__half* __restrict__ y)
{
    __shared__ __half sq[64 * LDQ];
    __shared__ __half sk[64 * LDQ];
    __shared__ __half sv[64 * LDQ];

    const int tid  = threadIdx.x;
    const int lane = tid & 31;
    const int warp = tid >> 5;
    const int qb = blockIdx.x;
    const int h  = blockIdx.y;
    const uint32_t sqb = smem_u32(sq);
    const uint32_t skb = smem_u32(sk);
    const uint32_t svb = smem_u32(sv);
    const float scale = 0.11180339887498949f;

    {
        const __half* qg = g_qh + ((size_t)h * S_LEN + qb * 64) * HEAD_DIM;
        #pragma unroll
        for (int p = 0; p < 5; p++) {
            const int idx = p * 128 + tid;
            const int r = idx / 10, seg = idx % 10;
            *(uint4*)(sq + r * LDQ + seg * 8) = *(const uint4*)(qg + r * 80 + seg * 8);
        }
    }
    __syncthreads();

    uint32_t qa[5][4];
    {
        const uint32_t a_off = (uint32_t)((warp * 16 + (lane & 15)) * LDQ + ((lane >> 4) << 3)) * 2;
        #pragma unroll
        for (int ks = 0; ks < 5; ks++) ldsm4(qa[ks], sqb + a_off + ks * 32);
    }

    float o[10][4];
    #pragma unroll
    for (int j = 0; j < 10; j++)
        #pragma unroll
        for (int e = 0; e < 4; e++) o[j][e] = 0.f;
    float mr0 = -1e30f, mr1 = -1e30f, lr0 = 0.f, lr1 = 0.f;

    const int row0 = qb * 64 + warp * 16 + (lane >> 2);
    const uint32_t b_off = (uint32_t)(((((lane >> 4) & 1) * 8 + (lane & 7)) * LDQ) + ((lane >> 3) & 1) * 8) * 2;
    const uint32_t v_off = (uint32_t)((lane & 15) * LDQ + ((lane >> 4) << 3)) * 2;

    for (int kb = 0; kb <= qb; kb++) {
        {
            const __half* kg = g_kh + ((size_t)h * S_LEN + kb * 64) * HEAD_DIM;
            const __half* vg = g_vh + ((size_t)h * S_LEN + kb * 64) * HEAD_DIM;
            #pragma unroll
            for (int p = 0; p < 5; p++) {
                const int idx = p * 128 + tid;
                const int r = idx / 10, seg = idx % 10;
                *(uint4*)(sk + r * LDQ + seg * 8) = *(const uint4*)(kg + r * 80 + seg * 8);
                *(uint4*)(sv + r * LDQ + seg * 8) = *(const uint4*)(vg + r * 80 + seg * 8);
            }
        }
        __syncthreads();

        float s[8][4];
        #pragma unroll
        for (int j = 0; j < 8; j++)
            #pragma unroll
            for (int e = 0; e < 4; e++) s[j][e] = 0.f;
        #pragma unroll
        for (int ks = 0; ks < 5; ks++) {
            #pragma unroll
            for (int p = 0; p < 4; p++) {
                uint32_t t[4];
                ldsm4(t, skb + b_off + (uint32_t)(p * 16 * LDQ) * 2 + ks * 32);
                mma16816(s[2 * p],     qa[ks], t);
                mma16816(s[2 * p + 1], qa[ks], t + 2);
            }
        }

        if (kb == qb) {
            #pragma unroll
            for (int j = 0; j < 8; j++)
                #pragma unroll
                for (int e = 0; e < 4; e++) {
                    const int col = kb * 64 + j * 8 + (lane & 3) * 2 + (e & 1);
                    const int row = row0 + (e >> 1) * 8;
                    s[j][e] = (col <= row) ? s[j][e] * scale : -1e30f;
                }
        } else {
            #pragma unroll
            for (int j = 0; j < 8; j++)
                #pragma unroll
                for (int e = 0; e < 4; e++) s[j][e] *= scale;
        }

        float m0 = -1e30f, m1 = -1e30f;
        #pragma unroll
        for (int j = 0; j < 8; j++) {
            m0 = fmaxf(m0, fmaxf(s[j][0], s[j][1]));
            m1 = fmaxf(m1, fmaxf(s[j][2], s[j][3]));
        }
        m0 = fmaxf(m0, __shfl_xor_sync(0xffffffffu, m0, 1));
        m0 = fmaxf(m0, __shfl_xor_sync(0xffffffffu, m0, 2));
        m1 = fmaxf(m1, __shfl_xor_sync(0xffffffffu, m1, 1));
        m1 = fmaxf(m1, __shfl_xor_sync(0xffffffffu, m1, 2));

        const float mn0 = fmaxf(mr0, m0), mn1 = fmaxf(mr1, m1);
        const float al0 = __expf(mr0 - mn0), al1 = __expf(mr1 - mn1);

        float lp0 = 0.f, lp1 = 0.f;
        #pragma unroll
        for (int j = 0; j < 8; j++) {
            s[j][0] = __expf(s[j][0] - mn0); lp0 += s[j][0];
            s[j][1] = __expf(s[j][1] - mn0); lp0 += s[j][1];
            s[j][2] = __expf(s[j][2] - mn1); lp1 += s[j][2];
            s[j][3] = __expf(s[j][3] - mn1); lp1 += s[j][3];
        }
        lp0 += __shfl_xor_sync(0xffffffffu, lp0, 1);
        lp0 += __shfl_xor_sync(0xffffffffu, lp0, 2);
        lp1 += __shfl_xor_sync(0xffffffffu, lp1, 1);
        lp1 += __shfl_xor_sync(0xffffffffu, lp1, 2);

        lr0 = lr0 * al0 + lp0;
        lr1 = lr1 * al1 + lp1;
        mr0 = mn0; mr1 = mn1;

        #pragma unroll
        for (int j = 0; j < 10; j++) {
            o[j][0] *= al0; o[j][1] *= al0;
            o[j][2] *= al1; o[j][3] *= al1;
        }

        uint32_t pa[4][4];
        #pragma unroll
        for (int ks2 = 0; ks2 < 4; ks2++) {
            pa[ks2][0] = pkf(s[2 * ks2][0],     s[2 * ks2][1]);
            pa[ks2][1] = pkf(s[2 * ks2][2],     s[2 * ks2][3]);
            pa[ks2][2] = pkf(s[2 * ks2 + 1][0], s[2 * ks2 + 1][1]);
            pa[ks2][3] = pkf(s[2 * ks2 + 1][2], s[2 * ks2 + 1][3]);
        }

        #pragma unroll
        for (int ks2 = 0; ks2 < 4; ks2++) {
            #pragma unroll
            for (int np = 0; np < 5; np++) {
                uint32_t t[4];
                ldsm4t(t, svb + v_off + (uint32_t)(ks2 * 16 * LDQ) * 2 + np * 32);
                mma16816(o[2 * np],     pa[ks2], t);
                mma16816(o[2 * np + 1], pa[ks2], t + 2);
            }
        }

        __syncthreads();
    }

    const float il0 = 1.f / lr0, il1 = 1.f / lr1;
    #pragma unroll
    for (int j = 0; j < 10; j++) {
        const int col = h * HEAD_DIM + j * 8 + (lane & 3) * 2;
        *(uint32_t*)(y + (size_t)row0 * DIM + col)       = pkf(o[j][0] * il0, o[j][1] * il0);
        *(uint32_t*)(y + (size_t)(row0 + 8) * DIM + col) = pkf(o[j][2] * il1, o[j][3] * il1);
    }
}

// ---------------- host launch ----------------
extern "C" void kernel_launch(void* const* d_in, const int* in_sizes, int n_in,
                              void* d_out, int out_size)
{
    const float* x       = (const float*)d_in[0];
    const int*   pos     = (const int*)  d_in[1];
    const float* ln_w    = (const float*)d_in[3];
    const float* ln_b    = (const float*)d_in[4];
    const float* wqkv_w  = (const float*)d_in[5];
    const float* wqkv_b  = (const float*)d_in[6];
    const float* wo_w    = (const float*)d_in[7];
    const float* wo_b    = (const float*)d_in[8];
    const float* w1_w    = (const float*)d_in[9];
    const float* w1_b    = (const float*)d_in[10];
    const float* w2_w    = (const float*)d_in[11];
    const float* w2_b    = (const float*)d_in[12];
    float* out = (float*)d_out;

    float *qkv_p, *attn_p;
    __half *h_p, *y_p, *ffn1_p;
    cudaGetSymbolAddress((void**)&h_p,    g_h);
    cudaGetSymbolAddress((void**)&qkv_p,  g_qkv);
    cudaGetSymbolAddress((void**)&y_p,    g_y);
    cudaGetSymbolAddress((void**)&attn_p, g_attn);
    cudaGetSymbolAddress((void**)&ffn1_p, g_ffn1);

    cudaFuncSetAttribute(mma_gemm<0>, cudaFuncAttributeMaxDynamicSharedMemorySize, SMEM_DYN);
    cudaFuncSetAttribute(mma_gemm<1>, cudaFuncAttributeMaxDynamicSharedMemorySize, SMEM_DYN);
    cudaFuncSetAttribute(mma_gemm<2>, cudaFuncAttributeMaxDynamicSharedMemorySize, SMEM_DYN);

    // 1. LayerNorm -> fp16 h
    ln_kernel<<<S_LEN, 256>>>(x, ln_w, ln_b);

    // 2. QKV projection (fp32 out for RoPE)
    mma_gemm<0><<<dim3(S_LEN / 128, 3 * DIM / 128), 256, SMEM_DYN>>>(
        h_p, wqkv_w, wqkv_b, qkv_p, nullptr, S_LEN, 3 * DIM, DIM, nullptr, nullptr);

    // 3. split + RoPE -> fp16
    prep_qkv_kernel<<<S_LEN, 256>>>(qkv_p, pos);

    // 4. tensor-core flash attention -> fp16 y
    attn_kernel<<<dim3(S_LEN / 64, N_HEAD), 128>>>(y_p);

    // 5. output projection -> fp32 attn
    mma_gemm<0><<<dim3(S_LEN / 128, DIM / 128), 256, SMEM_DYN>>>(
        y_p, wo_w, wo_b, attn_p, nullptr, S_LEN, DIM, DIM, nullptr, nullptr);

    // 6. FFN up + gelu -> fp16 ffn1
    mma_gemm<1><<<dim3(S_LEN / 128, INTER / 128), 256, SMEM_DYN>>>(
        h_p, w1_w, w1_b, nullptr, ffn1_p, S_LEN, INTER, DIM, nullptr, nullptr);

    // 7. FFN down + residual fuse
    mma_gemm<2><<<dim3(S_LEN / 128, DIM / 128), 256, SMEM_DYN>>>(
        ffn1_p, w2_w, w2_b, out, nullptr, S_LEN, DIM, INTER, attn_p, x);
}